// round 1
// baseline (speedup 1.0000x reference)
#include <cuda_runtime.h>
#include <cuda_bf16.h>
#include <cstdint>

// Problem constants
#define BS 4
#define SL 2048
#define NE 1024
#define NH 16
#define HD 64
#define MROWS (BS*SL)          // 8192

// ---------------- scratch (no allocs allowed) ----------------
__device__ float g_qkv[(size_t)MROWS * 3 * NE];   // [8192, 3072]
__device__ float g_y[(size_t)MROWS * NE];         // [8192, 1024]

// ---------------- SGEMM 128x128x8, 256 threads, 8x8 micro ----------------
#define GBM 128
#define GBN 128
#define GBK 8

__global__ __launch_bounds__(256) void sgemm_bias_kernel(
    const float* __restrict__ A, const float* __restrict__ B,
    const float* __restrict__ bias, float* __restrict__ C,
    int M, int N, int K)
{
    __shared__ float As[GBK][GBM];
    __shared__ float Bs[GBK][GBN];

    const int tid = threadIdx.x;
    const int bm = blockIdx.y * GBM;
    const int bn = blockIdx.x * GBN;

    const int tx = tid & 15;
    const int ty = tid >> 4;

    float acc[8][8];
    #pragma unroll
    for (int i = 0; i < 8; i++)
        #pragma unroll
        for (int j = 0; j < 8; j++) acc[i][j] = 0.f;

    const int arow = tid >> 1;          // 0..127
    const int acol = (tid & 1) * 4;     // 0 or 4
    const int brow = tid >> 5;          // 0..7
    const int bcol = (tid & 31) * 4;    // 0..124

    const float* Aptr = A + (size_t)(bm + arow) * K + acol;
    const float* Bptr = B + (size_t)brow * N + bn + bcol;

    for (int k0 = 0; k0 < K; k0 += GBK) {
        float4 a = *(const float4*)(Aptr + k0);
        float4 b = *(const float4*)(Bptr + (size_t)k0 * N);
        As[acol + 0][arow] = a.x;
        As[acol + 1][arow] = a.y;
        As[acol + 2][arow] = a.z;
        As[acol + 3][arow] = a.w;
        *(float4*)&Bs[brow][bcol] = b;
        __syncthreads();

        #pragma unroll
        for (int k = 0; k < GBK; k++) {
            float ra[8], rb[8];
            *(float4*)&ra[0] = *(const float4*)&As[k][ty * 8];
            *(float4*)&ra[4] = *(const float4*)&As[k][ty * 8 + 4];
            *(float4*)&rb[0] = *(const float4*)&Bs[k][tx * 8];
            *(float4*)&rb[4] = *(const float4*)&Bs[k][tx * 8 + 4];
            #pragma unroll
            for (int i = 0; i < 8; i++)
                #pragma unroll
                for (int j = 0; j < 8; j++)
                    acc[i][j] = fmaf(ra[i], rb[j], acc[i][j]);
        }
        __syncthreads();
    }

    #pragma unroll
    for (int i = 0; i < 8; i++) {
        const int row = bm + ty * 8 + i;
        #pragma unroll
        for (int j = 0; j < 8; j += 4) {
            const int col = bn + tx * 8 + j;
            float4 v;
            v.x = acc[i][j + 0] + bias[col + 0];
            v.y = acc[i][j + 1] + bias[col + 1];
            v.z = acc[i][j + 2] + bias[col + 2];
            v.w = acc[i][j + 3] + bias[col + 3];
            *(float4*)&C[(size_t)row * N + col] = v;
        }
    }
}

// ---------------- Flash attention (fp32, causal) ----------------
// One CTA per (batch-head, 64-row q tile). 256 threads:
//   thread -> (r = tid>>2) q-row within tile, (g = tid&3) column/dim group.
// smem rows padded to 68 floats (272B) so broadcast LDS.128 patterns are
// conflict-free (272 mod 128 = 16).
#define BQ 64
#define BKV 64
#define RSTR 68                        // floats per smem row
#define ATTN_SMEM (4 * BQ * RSTR * 4)  // Q,K,V,P = 69632 bytes

__global__ __launch_bounds__(256) void attn_kernel(
    const float* __restrict__ qkv, float* __restrict__ y)
{
    extern __shared__ float sm[];
    float* Qs = sm;
    float* Ks = Qs + BQ * RSTR;
    float* Vs = Ks + BQ * RSTR;
    float* Ps = Vs + BQ * RSTR;

    const int tid = threadIdx.x;
    const int qt = blockIdx.x;
    const int bh = blockIdx.y;
    const int b = bh >> 4;
    const int h = bh & 15;
    const int q0 = qt * BQ;

    const int r = tid >> 2;   // q-row in tile (0..63)
    const int g = tid & 3;    // group (0..3)

    // ---- load Q tile ----
    {
        const float* src = qkv + ((size_t)(b * SL + q0 + r)) * (3 * NE) + h * HD;
        float4* dst = (float4*)(Qs + r * RSTR);
        #pragma unroll
        for (int i = 0; i < 4; i++) {
            const int c4 = g + 4 * i;
            dst[c4] = *(const float4*)(src + c4 * 4);
        }
    }

    float m = -1e30f, l = 0.f;
    float4 accO[4];
    #pragma unroll
    for (int i = 0; i < 4; i++) accO[i] = make_float4(0.f, 0.f, 0.f, 0.f);

    const float scale = 0.125f;  // 1/sqrt(64)
    const int qg = q0 + r;

    for (int k0 = 0; k0 <= q0; k0 += BKV) {
        __syncthreads();  // prev iter's P/V use done before overwrite
        // ---- load K,V tiles ----
        {
            const float* ksrc = qkv + ((size_t)(b * SL + k0 + r)) * (3 * NE) + NE + h * HD;
            const float* vsrc = ksrc + NE;
            float4* kdst = (float4*)(Ks + r * RSTR);
            float4* vdst = (float4*)(Vs + r * RSTR);
            #pragma unroll
            for (int i = 0; i < 4; i++) {
                const int c4 = g + 4 * i;
                kdst[c4] = *(const float4*)(ksrc + c4 * 4);
                vdst[c4] = *(const float4*)(vsrc + c4 * 4);
            }
        }
        __syncthreads();

        // ---- S = scale * Q K^T, cols c = g + 4*ci ----
        float s[16];
        #pragma unroll
        for (int ci = 0; ci < 16; ci++) s[ci] = 0.f;
        const float4* qrow = (const float4*)(Qs + r * RSTR);
        #pragma unroll 4
        for (int d4 = 0; d4 < 16; d4++) {
            const float4 q = qrow[d4];
            #pragma unroll
            for (int ci = 0; ci < 16; ci++) {
                const float4 kv = *(const float4*)(Ks + (g + 4 * ci) * RSTR + d4 * 4);
                s[ci] = fmaf(q.x, kv.x, s[ci]);
                s[ci] = fmaf(q.y, kv.y, s[ci]);
                s[ci] = fmaf(q.z, kv.z, s[ci]);
                s[ci] = fmaf(q.w, kv.w, s[ci]);
            }
        }

        // ---- mask (diagonal tile only) + online softmax ----
        const bool diag = (k0 == q0);
        float mt = -1e30f;
        #pragma unroll
        for (int ci = 0; ci < 16; ci++) {
            float v = s[ci] * scale;
            if (diag && (k0 + g + 4 * ci) > qg) v = -1e30f;
            s[ci] = v;
            mt = fmaxf(mt, v);
        }
        mt = fmaxf(mt, __shfl_xor_sync(0xFFFFFFFFu, mt, 1));
        mt = fmaxf(mt, __shfl_xor_sync(0xFFFFFFFFu, mt, 2));
        const float mnew = fmaxf(m, mt);
        const float corr = __expf(m - mnew);
        float lsum = 0.f;
        #pragma unroll
        for (int ci = 0; ci < 16; ci++) {
            const float p = __expf(s[ci] - mnew);
            s[ci] = p;
            lsum += p;
        }
        lsum += __shfl_xor_sync(0xFFFFFFFFu, lsum, 1);
        lsum += __shfl_xor_sync(0xFFFFFFFFu, lsum, 2);
        l = l * corr + lsum;
        m = mnew;
        #pragma unroll
        for (int i = 0; i < 4; i++) {
            accO[i].x *= corr; accO[i].y *= corr;
            accO[i].z *= corr; accO[i].w *= corr;
        }

        // ---- stage P (only own warp reads these rows) ----
        #pragma unroll
        for (int ci = 0; ci < 16; ci++)
            Ps[r * RSTR + g + 4 * ci] = s[ci];
        __syncwarp();

        // ---- O += P V ----
        const float* prow = Ps + r * RSTR;
        #pragma unroll 4
        for (int j4 = 0; j4 < 16; j4++) {
            const float4 p4 = *(const float4*)(prow + 4 * j4);
            const float pj[4] = {p4.x, p4.y, p4.z, p4.w};
            #pragma unroll
            for (int jj = 0; jj < 4; jj++) {
                const float p = pj[jj];
                const float4* vrow = (const float4*)(Vs + (4 * j4 + jj) * RSTR);
                #pragma unroll
                for (int i = 0; i < 4; i++) {
                    const float4 v = vrow[g + 4 * i];
                    accO[i].x = fmaf(p, v.x, accO[i].x);
                    accO[i].y = fmaf(p, v.y, accO[i].y);
                    accO[i].z = fmaf(p, v.z, accO[i].z);
                    accO[i].w = fmaf(p, v.w, accO[i].w);
                }
            }
        }
        __syncwarp();
    }

    // ---- epilogue: normalize + write y in [bs, sl, ne] layout ----
    const float invl = 1.f / l;
    float* dst = y + ((size_t)(b * SL + q0 + r)) * NE + h * HD;
    #pragma unroll
    for (int i = 0; i < 4; i++) {
        const int c4 = g + 4 * i;
        float4 o = accO[i];
        o.x *= invl; o.y *= invl; o.z *= invl; o.w *= invl;
        *(float4*)(dst + c4 * 4) = o;
    }
}

// ---------------- launch ----------------
extern "C" void kernel_launch(void* const* d_in, const int* in_sizes, int n_in,
                              void* d_out, int out_size)
{
    const float* x    = (const float*)d_in[0];
    // d_in[1] = mask (int32) — causal, handled analytically
    const float* Wqkv = (const float*)d_in[2];
    const float* bqkv = (const float*)d_in[3];
    const float* Wo   = (const float*)d_in[4];
    const float* bo   = (const float*)d_in[5];
    float* out = (float*)d_out;

    float* qkv = nullptr;
    float* ybuf = nullptr;
    cudaGetSymbolAddress((void**)&qkv, g_qkv);
    cudaGetSymbolAddress((void**)&ybuf, g_y);

    // 1) QKV projection: [8192,1024] @ [1024,3072] + bias
    {
        dim3 grid((3 * NE) / GBN, MROWS / GBM);
        sgemm_bias_kernel<<<grid, 256>>>(x, Wqkv, bqkv, qkv, MROWS, 3 * NE, NE);
    }

    // 2) causal flash attention
    {
        cudaFuncSetAttribute(attn_kernel,
                             cudaFuncAttributeMaxDynamicSharedMemorySize, ATTN_SMEM);
        dim3 grid(SL / BQ, BS * NH);
        attn_kernel<<<grid, 256, ATTN_SMEM>>>(qkv, ybuf);
    }

    // 3) output projection: [8192,1024] @ [1024,1024] + bias
    {
        dim3 grid(NE / GBN, MROWS / GBM);
        sgemm_bias_kernel<<<grid, 256>>>(ybuf, Wo, bo, out, MROWS, NE, NE);
    }
}

// round 5
// speedup vs baseline: 1.3229x; 1.3229x over previous
#include <cuda_runtime.h>
#include <cuda_bf16.h>
#include <cstdint>

// Problem constants
#define BS 4
#define SL 2048
#define NE 1024
#define NH 16
#define HD 64
#define MROWS (BS*SL)          // 8192
#define GK 1024                // K dim for both GEMMs
#define BKC 32                 // K per chunk (bf16 elems)
#define NCH (GK / BKC)         // 32 chunks

// ---------------- scratch (no allocs allowed) ----------------
__device__ float g_qkv[(size_t)MROWS * 3 * NE];   // [8192, 3072]
__device__ float g_y[(size_t)MROWS * NE];         // [8192, 1024]
__device__ __nv_bfloat16 g_xh[(size_t)MROWS * NE];
__device__ __nv_bfloat16 g_xl[(size_t)MROWS * NE];
__device__ __nv_bfloat16 g_yh[(size_t)MROWS * NE];
__device__ __nv_bfloat16 g_yl[(size_t)MROWS * NE];
__device__ __nv_bfloat16 g_wqh[(size_t)3 * NE * NE];  // [3072,1024] (transposed)
__device__ __nv_bfloat16 g_wql[(size_t)3 * NE * NE];
__device__ __nv_bfloat16 g_woh[(size_t)NE * NE];      // [1024,1024] (transposed)
__device__ __nv_bfloat16 g_wol[(size_t)NE * NE];

// ---------------- helpers ----------------
__device__ __forceinline__ uint32_t smem_u32(const void* p) {
    uint32_t a;
    asm("{ .reg .u64 t; cvta.to.shared.u64 t, %1; cvt.u32.u64 %0, t; }" : "=r"(a) : "l"(p));
    return a;
}
__device__ __forceinline__ void cp_async16(uint32_t dst, const void* src) {
    asm volatile("cp.async.cg.shared.global [%0], [%1], 16;" :: "r"(dst), "l"(src) : "memory");
}
__device__ __forceinline__ void cp_commit() {
    asm volatile("cp.async.commit_group;" ::: "memory");
}
__device__ __forceinline__ void ldmatrix_x4(uint32_t* r, uint32_t addr) {
    asm volatile("ldmatrix.sync.aligned.m8n8.x4.shared.b16 {%0,%1,%2,%3}, [%4];"
                 : "=r"(r[0]), "=r"(r[1]), "=r"(r[2]), "=r"(r[3]) : "r"(addr));
}
__device__ __forceinline__ void ldmatrix_x2(uint32_t* r, uint32_t addr) {
    asm volatile("ldmatrix.sync.aligned.m8n8.x2.shared.b16 {%0,%1}, [%2];"
                 : "=r"(r[0]), "=r"(r[1]) : "r"(addr));
}
__device__ __forceinline__ void mma_bf16(float* c, const uint32_t* a, const uint32_t* b) {
    asm volatile(
        "mma.sync.aligned.m16n8k16.row.col.f32.bf16.bf16.f32 "
        "{%0,%1,%2,%3}, {%4,%5,%6,%7}, {%8,%9}, {%0,%1,%2,%3};"
        : "+f"(c[0]), "+f"(c[1]), "+f"(c[2]), "+f"(c[3])
        : "r"(a[0]), "r"(a[1]), "r"(a[2]), "r"(a[3]), "r"(b[0]), "r"(b[1]));
}

// ---------------- split kernels ----------------
__global__ __launch_bounds__(256) void split_kernel(
    const float* __restrict__ in, __nv_bfloat16* __restrict__ hi,
    __nv_bfloat16* __restrict__ lo, int n4)
{
    int i = blockIdx.x * 256 + threadIdx.x;
    if (i >= n4) return;
    float4 v = ((const float4*)in)[i];
    __nv_bfloat16 hx = __float2bfloat16(v.x), hy = __float2bfloat16(v.y);
    __nv_bfloat16 hz = __float2bfloat16(v.z), hw = __float2bfloat16(v.w);
    __nv_bfloat162* H = (__nv_bfloat162*)hi;
    __nv_bfloat162* L = (__nv_bfloat162*)lo;
    H[2 * i + 0] = __nv_bfloat162(hx, hy);
    H[2 * i + 1] = __nv_bfloat162(hz, hw);
    L[2 * i + 0] = __nv_bfloat162(__float2bfloat16(v.x - __bfloat162float(hx)),
                                  __float2bfloat16(v.y - __bfloat162float(hy)));
    L[2 * i + 1] = __nv_bfloat162(__float2bfloat16(v.z - __bfloat162float(hz)),
                                  __float2bfloat16(v.w - __bfloat162float(hw)));
}

// transpose + split: W [Kd, Nd] fp32 -> hi/lo [Nd, Kd] bf16
__global__ __launch_bounds__(256) void tsplit_kernel(
    const float* __restrict__ W, __nv_bfloat16* __restrict__ hi,
    __nv_bfloat16* __restrict__ lo, int Kd, int Nd)
{
    __shared__ float t[32][33];
    const int tx = threadIdx.x & 31, ty = threadIdx.x >> 5;  // 32 x 8
    const int k0 = blockIdx.y * 32, n0 = blockIdx.x * 32;
    #pragma unroll
    for (int r = 0; r < 4; r++)
        t[ty + 8 * r][tx] = W[(size_t)(k0 + ty + 8 * r) * Nd + n0 + tx];
    __syncthreads();
    #pragma unroll
    for (int r = 0; r < 4; r++) {
        float v = t[tx][ty + 8 * r];
        __nv_bfloat16 h = __float2bfloat16(v);
        size_t o = (size_t)(n0 + ty + 8 * r) * Kd + k0 + tx;
        hi[o] = h;
        lo[o] = __float2bfloat16(v - __bfloat162float(h));
    }
}

// ---------------- HMMA bf16x3 GEMM ----------------
// C[M,N] = A@B + bias. A hi/lo [M,GK] bf16, B hi/lo [N,GK] bf16 (row = output col).
// CTA 128x128, K chunks of 32, cp.async double buffer, mma.sync m16n8k16.
#define SROWB 80                       // padded smem row bytes (64B data + 16B pad)
#define TILEB (128 * SROWB)            // 10240
#define STAGEB (4 * TILEB)             // Ah, Al, Bh, Bl = 40960
#define GEMM_SMEM (2 * STAGEB)         // 81920

__global__ __launch_bounds__(256)
void gemm_bf16x3(const __nv_bfloat16* __restrict__ Ah, const __nv_bfloat16* __restrict__ Al,
                 const __nv_bfloat16* __restrict__ Bh, const __nv_bfloat16* __restrict__ Bl,
                 const float* __restrict__ bias, float* __restrict__ C, int N)
{
    extern __shared__ __align__(128) char smem[];
    const int tid = threadIdx.x;
    const int wid = tid >> 5;
    const int lane = tid & 31;
    const int bm = blockIdx.y * 128;
    const int bn = blockIdx.x * 128;
    const uint32_t sbase = smem_u32(smem);

    // warp tile: 64 rows (wm) x 32 cols (wn)
    const int wm = wid & 1;
    const int wn = wid >> 1;

    float acc[4][4][4];
    #pragma unroll
    for (int mi = 0; mi < 4; mi++)
        #pragma unroll
        for (int ni = 0; ni < 4; ni++)
            #pragma unroll
            for (int e = 0; e < 4; e++) acc[mi][ni][e] = 0.f;

    // ---- chunk loader: 4 tiles of 128 rows x 64B, padded to 80B rows ----
    auto load_chunk = [&](int c, int st) {
        const uint32_t sb = sbase + st * STAGEB;
        const __nv_bfloat16* srcs[4] = {Ah, Al, Bh, Bl};
        const int r0s[4] = {bm, bm, bn, bn};
        #pragma unroll
        for (int t = 0; t < 4; t++) {
            const char* G = (const char*)srcs[t];
            #pragma unroll
            for (int i = 0; i < 2; i++) {
                const int lin = tid + 256 * i;            // 0..511
                const int row = lin >> 2, g = lin & 3;
                const uint32_t dst = sb + t * TILEB + row * SROWB + g * 16;
                const char* src = G + (size_t)(r0s[t] + row) * (GK * 2)
                                    + (size_t)c * (BKC * 2) + g * 16;
                cp_async16(dst, src);
            }
        }
    };

    // ---- compute one chunk from stage st ----
    auto compute = [&](int st) {
        const uint32_t tAh = sbase + st * STAGEB;
        const uint32_t tAl = tAh + TILEB;
        const uint32_t tBh = tAh + 2 * TILEB;
        const uint32_t tBl = tAh + 3 * TILEB;
        #pragma unroll
        for (int ks = 0; ks < 2; ks++) {
            uint32_t fah[4][4], fal[4][4], fbh[4][2], fbl[4][2];
            #pragma unroll
            for (int mi = 0; mi < 4; mi++) {
                const int row = wm * 64 + mi * 16 + (lane & 15);
                const uint32_t off = row * SROWB + ks * 32 + (lane >> 4) * 16;
                ldmatrix_x4(fah[mi], tAh + off);
                ldmatrix_x4(fal[mi], tAl + off);
            }
            #pragma unroll
            for (int ni = 0; ni < 4; ni++) {
                const int nrow = wn * 32 + ni * 8 + (lane & 7);
                const uint32_t off = nrow * SROWB + ks * 32 + ((lane >> 3) & 1) * 16;
                ldmatrix_x2(fbh[ni], tBh + off);
                ldmatrix_x2(fbl[ni], tBl + off);
            }
            #pragma unroll
            for (int mi = 0; mi < 4; mi++)
                #pragma unroll
                for (int ni = 0; ni < 4; ni++) {
                    mma_bf16(acc[mi][ni], fah[mi], fbh[ni]);
                    mma_bf16(acc[mi][ni], fah[mi], fbl[ni]);
                    mma_bf16(acc[mi][ni], fal[mi], fbh[ni]);
                }
        }
    };

    // ---- pipeline ----
    load_chunk(0, 0);
    cp_commit();
    for (int c = 0; c < NCH; c++) {
        const int s = c & 1;
        if (c + 1 < NCH) {
            load_chunk(c + 1, s ^ 1);
            cp_commit();
            asm volatile("cp.async.wait_group 1;" ::: "memory");
        } else {
            asm volatile("cp.async.wait_group 0;" ::: "memory");
        }
        __syncthreads();
        compute(s);
        __syncthreads();
    }

    // ---- epilogue: bias + store ----
    #pragma unroll
    for (int mi = 0; mi < 4; mi++) {
        const int r0 = bm + wm * 64 + mi * 16 + (lane >> 2);
        #pragma unroll
        for (int ni = 0; ni < 4; ni++) {
            const int c0 = bn + wn * 32 + ni * 8 + (lane & 3) * 2;
            const float2 bv = *(const float2*)(bias + c0);
            float2 o0, o1;
            o0.x = acc[mi][ni][0] + bv.x;
            o0.y = acc[mi][ni][1] + bv.y;
            o1.x = acc[mi][ni][2] + bv.x;
            o1.y = acc[mi][ni][3] + bv.y;
            *(float2*)(C + (size_t)r0 * N + c0) = o0;
            *(float2*)(C + (size_t)(r0 + 8) * N + c0) = o1;
        }
    }
}

// ---------------- Flash attention (fp32, causal) ----------------
#define BQ 64
#define BKV 64
#define RSTR 68
#define ATTN_SMEM (4 * BQ * RSTR * 4)

__global__ __launch_bounds__(256) void attn_kernel(
    const float* __restrict__ qkv, float* __restrict__ y)
{
    extern __shared__ float sm[];
    float* Qs = sm;
    float* Ks = Qs + BQ * RSTR;
    float* Vs = Ks + BQ * RSTR;
    float* Ps = Vs + BQ * RSTR;

    const int tid = threadIdx.x;
    const int qt = blockIdx.x;
    const int bh = blockIdx.y;
    const int b = bh >> 4;
    const int h = bh & 15;
    const int q0 = qt * BQ;

    const int r = tid >> 2;
    const int g = tid & 3;

    {
        const float* src = qkv + ((size_t)(b * SL + q0 + r)) * (3 * NE) + h * HD;
        float4* dst = (float4*)(Qs + r * RSTR);
        #pragma unroll
        for (int i = 0; i < 4; i++) {
            const int c4 = g + 4 * i;
            dst[c4] = *(const float4*)(src + c4 * 4);
        }
    }

    float m = -1e30f, l = 0.f;
    float4 accO[4];
    #pragma unroll
    for (int i = 0; i < 4; i++) accO[i] = make_float4(0.f, 0.f, 0.f, 0.f);

    const float scale = 0.125f;
    const int qg = q0 + r;

    for (int k0 = 0; k0 <= q0; k0 += BKV) {
        __syncthreads();
        {
            const float* ksrc = qkv + ((size_t)(b * SL + k0 + r)) * (3 * NE) + NE + h * HD;
            const float* vsrc = ksrc + NE;
            float4* kdst = (float4*)(Ks + r * RSTR);
            float4* vdst = (float4*)(Vs + r * RSTR);
            #pragma unroll
            for (int i = 0; i < 4; i++) {
                const int c4 = g + 4 * i;
                kdst[c4] = *(const float4*)(ksrc + c4 * 4);
                vdst[c4] = *(const float4*)(vsrc + c4 * 4);
            }
        }
        __syncthreads();

        float s[16];
        #pragma unroll
        for (int ci = 0; ci < 16; ci++) s[ci] = 0.f;
        const float4* qrow = (const float4*)(Qs + r * RSTR);
        #pragma unroll 4
        for (int d4 = 0; d4 < 16; d4++) {
            const float4 q = qrow[d4];
            #pragma unroll
            for (int ci = 0; ci < 16; ci++) {
                const float4 kv = *(const float4*)(Ks + (g + 4 * ci) * RSTR + d4 * 4);
                s[ci] = fmaf(q.x, kv.x, s[ci]);
                s[ci] = fmaf(q.y, kv.y, s[ci]);
                s[ci] = fmaf(q.z, kv.z, s[ci]);
                s[ci] = fmaf(q.w, kv.w, s[ci]);
            }
        }

        const bool diag = (k0 == q0);
        float mt = -1e30f;
        #pragma unroll
        for (int ci = 0; ci < 16; ci++) {
            float v = s[ci] * scale;
            if (diag && (k0 + g + 4 * ci) > qg) v = -1e30f;
            s[ci] = v;
            mt = fmaxf(mt, v);
        }
        mt = fmaxf(mt, __shfl_xor_sync(0xFFFFFFFFu, mt, 1));
        mt = fmaxf(mt, __shfl_xor_sync(0xFFFFFFFFu, mt, 2));
        const float mnew = fmaxf(m, mt);
        const float corr = __expf(m - mnew);
        float lsum = 0.f;
        #pragma unroll
        for (int ci = 0; ci < 16; ci++) {
            const float p = __expf(s[ci] - mnew);
            s[ci] = p;
            lsum += p;
        }
        lsum += __shfl_xor_sync(0xFFFFFFFFu, lsum, 1);
        lsum += __shfl_xor_sync(0xFFFFFFFFu, lsum, 2);
        l = l * corr + lsum;
        m = mnew;
        #pragma unroll
        for (int i = 0; i < 4; i++) {
            accO[i].x *= corr; accO[i].y *= corr;
            accO[i].z *= corr; accO[i].w *= corr;
        }

        #pragma unroll
        for (int ci = 0; ci < 16; ci++)
            Ps[r * RSTR + g + 4 * ci] = s[ci];
        __syncwarp();

        const float* prow = Ps + r * RSTR;
        #pragma unroll 4
        for (int j4 = 0; j4 < 16; j4++) {
            const float4 p4 = *(const float4*)(prow + 4 * j4);
            const float pj[4] = {p4.x, p4.y, p4.z, p4.w};
            #pragma unroll
            for (int jj = 0; jj < 4; jj++) {
                const float p = pj[jj];
                const float4* vrow = (const float4*)(Vs + (4 * j4 + jj) * RSTR);
                #pragma unroll
                for (int i = 0; i < 4; i++) {
                    const float4 v = vrow[g + 4 * i];
                    accO[i].x = fmaf(p, v.x, accO[i].x);
                    accO[i].y = fmaf(p, v.y, accO[i].y);
                    accO[i].z = fmaf(p, v.z, accO[i].z);
                    accO[i].w = fmaf(p, v.w, accO[i].w);
                }
            }
        }
        __syncwarp();
    }

    const float invl = 1.f / l;
    float* dst = y + ((size_t)(b * SL + q0 + r)) * NE + h * HD;
    #pragma unroll
    for (int i = 0; i < 4; i++) {
        const int c4 = g + 4 * i;
        float4 o = accO[i];
        o.x *= invl; o.y *= invl; o.z *= invl; o.w *= invl;
        *(float4*)(dst + c4 * 4) = o;
    }
}

// ---------------- launch ----------------
extern "C" void kernel_launch(void* const* d_in, const int* in_sizes, int n_in,
                              void* d_out, int out_size)
{
    const float* x    = (const float*)d_in[0];
    const float* Wqkv = (const float*)d_in[2];
    const float* bqkv = (const float*)d_in[3];
    const float* Wo   = (const float*)d_in[4];
    const float* bo   = (const float*)d_in[5];
    float* out = (float*)d_out;

    float *qkv, *ybuf;
    __nv_bfloat16 *xh, *xl, *yh, *yl, *wqh, *wql, *woh, *wol;
    cudaGetSymbolAddress((void**)&qkv, g_qkv);
    cudaGetSymbolAddress((void**)&ybuf, g_y);
    cudaGetSymbolAddress((void**)&xh, g_xh);
    cudaGetSymbolAddress((void**)&xl, g_xl);
    cudaGetSymbolAddress((void**)&yh, g_yh);
    cudaGetSymbolAddress((void**)&yl, g_yl);
    cudaGetSymbolAddress((void**)&wqh, g_wqh);
    cudaGetSymbolAddress((void**)&wql, g_wql);
    cudaGetSymbolAddress((void**)&woh, g_woh);
    cudaGetSymbolAddress((void**)&wol, g_wol);

    cudaFuncSetAttribute(gemm_bf16x3, cudaFuncAttributeMaxDynamicSharedMemorySize, GEMM_SMEM);
    cudaFuncSetAttribute(attn_kernel, cudaFuncAttributeMaxDynamicSharedMemorySize, ATTN_SMEM);

    // split inputs / weights
    split_kernel<<<(MROWS * NE / 4 + 255) / 256, 256>>>(x, xh, xl, MROWS * NE / 4);
    tsplit_kernel<<<dim3(3 * NE / 32, NE / 32), 256>>>(Wqkv, wqh, wql, NE, 3 * NE);
    tsplit_kernel<<<dim3(NE / 32, NE / 32), 256>>>(Wo, woh, wol, NE, NE);

    // 1) QKV projection (HMMA bf16x3)
    gemm_bf16x3<<<dim3(3 * NE / 128, MROWS / 128), 256, GEMM_SMEM>>>(
        xh, xl, wqh, wql, bqkv, qkv, 3 * NE);

    // 2) causal flash attention (fp32)
    attn_kernel<<<dim3(SL / BQ, BS * NH), 256, ATTN_SMEM>>>(qkv, ybuf);

    // 3) output projection (HMMA bf16x3)
    split_kernel<<<(MROWS * NE / 4 + 255) / 256, 256>>>(ybuf, yh, yl, MROWS * NE / 4);
    gemm_bf16x3<<<dim3(NE / 128, MROWS / 128), 256, GEMM_SMEM>>>(
        yh, yl, woh, wol, bo, out, NE);
}

// round 8
// speedup vs baseline: 2.3833x; 1.8016x over previous
#include <cuda_runtime.h>
#include <cuda_bf16.h>
#include <cstdint>

// Problem constants
#define BS 4
#define SL 2048
#define NE 1024
#define NH 16
#define HD 64
#define MROWS (BS*SL)          // 8192
#define GK 1024                // K dim for both GEMMs
#define BKC 32                 // K per chunk (bf16 elems)
#define NCH (GK / BKC)         // 32 chunks

// ---------------- scratch (no allocs allowed) ----------------
__device__ float g_qkv[(size_t)MROWS * 3 * NE];   // [8192, 3072]
__device__ float g_y[(size_t)MROWS * NE];         // [8192, 1024]
__device__ __nv_bfloat16 g_xh[(size_t)MROWS * NE];
__device__ __nv_bfloat16 g_xl[(size_t)MROWS * NE];
__device__ __nv_bfloat16 g_yh[(size_t)MROWS * NE];
__device__ __nv_bfloat16 g_yl[(size_t)MROWS * NE];
__device__ __nv_bfloat16 g_wqh[(size_t)3 * NE * NE];  // [3072,1024] (transposed)
__device__ __nv_bfloat16 g_wql[(size_t)3 * NE * NE];
__device__ __nv_bfloat16 g_woh[(size_t)NE * NE];      // [1024,1024] (transposed)
__device__ __nv_bfloat16 g_wol[(size_t)NE * NE];
// attention operands, per (b,h): Q/K [SL, HD], Vt [HD, SL], hi/lo split
#define BHN (BS * NH)   // 64
__device__ __nv_bfloat16 g_aqh[(size_t)BHN * SL * HD];
__device__ __nv_bfloat16 g_aql[(size_t)BHN * SL * HD];
__device__ __nv_bfloat16 g_akh[(size_t)BHN * SL * HD];
__device__ __nv_bfloat16 g_akl[(size_t)BHN * SL * HD];
__device__ __nv_bfloat16 g_avth[(size_t)BHN * HD * SL];
__device__ __nv_bfloat16 g_avtl[(size_t)BHN * HD * SL];

// ---------------- helpers ----------------
__device__ __forceinline__ uint32_t smem_u32(const void* p) {
    uint32_t a;
    asm("{ .reg .u64 t; cvta.to.shared.u64 t, %1; cvt.u32.u64 %0, t; }" : "=r"(a) : "l"(p));
    return a;
}
__device__ __forceinline__ void cp_async16(uint32_t dst, const void* src) {
    asm volatile("cp.async.cg.shared.global [%0], [%1], 16;" :: "r"(dst), "l"(src) : "memory");
}
__device__ __forceinline__ void cp_commit() {
    asm volatile("cp.async.commit_group;" ::: "memory");
}
__device__ __forceinline__ void ldmatrix_x4(uint32_t* r, uint32_t addr) {
    asm volatile("ldmatrix.sync.aligned.m8n8.x4.shared.b16 {%0,%1,%2,%3}, [%4];"
                 : "=r"(r[0]), "=r"(r[1]), "=r"(r[2]), "=r"(r[3]) : "r"(addr));
}
__device__ __forceinline__ void ldmatrix_x2(uint32_t* r, uint32_t addr) {
    asm volatile("ldmatrix.sync.aligned.m8n8.x2.shared.b16 {%0,%1}, [%2];"
                 : "=r"(r[0]), "=r"(r[1]) : "r"(addr));
}
__device__ __forceinline__ void mma_bf16(float* c, const uint32_t* a, uint32_t b0, uint32_t b1) {
    asm volatile(
        "mma.sync.aligned.m16n8k16.row.col.f32.bf16.bf16.f32 "
        "{%0,%1,%2,%3}, {%4,%5,%6,%7}, {%8,%9}, {%0,%1,%2,%3};"
        : "+f"(c[0]), "+f"(c[1]), "+f"(c[2]), "+f"(c[3])
        : "r"(a[0]), "r"(a[1]), "r"(a[2]), "r"(a[3]), "r"(b0), "r"(b1));
}
// split pair of floats into hi/lo bf16x2 packed regs (low bf16 = first arg)
__device__ __forceinline__ void split2(float a, float b, uint32_t& hi, uint32_t& lo) {
    __nv_bfloat162 h2 = __floats2bfloat162_rn(a, b);
    hi = *reinterpret_cast<uint32_t*>(&h2);
    __nv_bfloat162 l2 = __floats2bfloat162_rn(a - __bfloat162float(h2.x),
                                              b - __bfloat162float(h2.y));
    lo = *reinterpret_cast<uint32_t*>(&l2);
}

// ---------------- split kernels ----------------
__global__ __launch_bounds__(256) void split_kernel(
    const float* __restrict__ in, __nv_bfloat16* __restrict__ hi,
    __nv_bfloat16* __restrict__ lo, int n4)
{
    int i = blockIdx.x * 256 + threadIdx.x;
    if (i >= n4) return;
    float4 v = ((const float4*)in)[i];
    __nv_bfloat16 hx = __float2bfloat16(v.x), hy = __float2bfloat16(v.y);
    __nv_bfloat16 hz = __float2bfloat16(v.z), hw = __float2bfloat16(v.w);
    __nv_bfloat162* H = (__nv_bfloat162*)hi;
    __nv_bfloat162* L = (__nv_bfloat162*)lo;
    H[2 * i + 0] = __nv_bfloat162(hx, hy);
    H[2 * i + 1] = __nv_bfloat162(hz, hw);
    L[2 * i + 0] = __nv_bfloat162(__float2bfloat16(v.x - __bfloat162float(hx)),
                                  __float2bfloat16(v.y - __bfloat162float(hy)));
    L[2 * i + 1] = __nv_bfloat162(__float2bfloat16(v.z - __bfloat162float(hz)),
                                  __float2bfloat16(v.w - __bfloat162float(hw)));
}

// transpose + split: W [Kd, Nd] fp32 -> hi/lo [Nd, Kd] bf16
__global__ __launch_bounds__(256) void tsplit_kernel(
    const float* __restrict__ W, __nv_bfloat16* __restrict__ hi,
    __nv_bfloat16* __restrict__ lo, int Kd, int Nd)
{
    __shared__ float t[32][33];
    const int tx = threadIdx.x & 31, ty = threadIdx.x >> 5;  // 32 x 8
    const int k0 = blockIdx.y * 32, n0 = blockIdx.x * 32;
    #pragma unroll
    for (int r = 0; r < 4; r++)
        t[ty + 8 * r][tx] = W[(size_t)(k0 + ty + 8 * r) * Nd + n0 + tx];
    __syncthreads();
    #pragma unroll
    for (int r = 0; r < 4; r++) {
        float v = t[tx][ty + 8 * r];
        __nv_bfloat16 h = __float2bfloat16(v);
        size_t o = (size_t)(n0 + ty + 8 * r) * Kd + k0 + tx;
        hi[o] = h;
        lo[o] = __float2bfloat16(v - __bfloat162float(h));
    }
}

// ---------------- attention prep: qkv -> per-head bf16 hi/lo ----------------
// Q (scaled by 1/8) and K: [bh][s][d]
__global__ __launch_bounds__(256) void qk_prep(
    const float* __restrict__ qkv,
    __nv_bfloat16* __restrict__ qh, __nv_bfloat16* __restrict__ ql,
    __nv_bfloat16* __restrict__ kh, __nv_bfloat16* __restrict__ kl)
{
    const int idx = blockIdx.x * 256 + threadIdx.x;   // BHN*SL*16
    const int dg = idx & 15;
    const int s  = (idx >> 4) & (SL - 1);
    const int bh = idx >> 15;
    const int b = bh >> 4, h = bh & 15;
    const float* src = qkv + ((size_t)(b * SL + s)) * (3 * NE) + h * HD + dg * 4;
    float4 q = *(const float4*)src;
    float4 k = *(const float4*)(src + NE);
    q.x *= 0.125f; q.y *= 0.125f; q.z *= 0.125f; q.w *= 0.125f;
    const size_t o = (((size_t)bh * SL + s) * HD + dg * 4) / 2;  // bf16x2 index
    __nv_bfloat162* QH = (__nv_bfloat162*)qh; __nv_bfloat162* QL = (__nv_bfloat162*)ql;
    __nv_bfloat162* KH = (__nv_bfloat162*)kh; __nv_bfloat162* KL = (__nv_bfloat162*)kl;
    uint32_t h0, l0, h1, l1;
    split2(q.x, q.y, h0, l0); split2(q.z, q.w, h1, l1);
    QH[o] = *(__nv_bfloat162*)&h0; QH[o + 1] = *(__nv_bfloat162*)&h1;
    QL[o] = *(__nv_bfloat162*)&l0; QL[o + 1] = *(__nv_bfloat162*)&l1;
    split2(k.x, k.y, h0, l0); split2(k.z, k.w, h1, l1);
    KH[o] = *(__nv_bfloat162*)&h0; KH[o + 1] = *(__nv_bfloat162*)&h1;
    KL[o] = *(__nv_bfloat162*)&l0; KL[o + 1] = *(__nv_bfloat162*)&l1;
}

// V transpose + split: Vt[bh][d][s]
__global__ __launch_bounds__(256) void vt_prep(
    const float* __restrict__ qkv,
    __nv_bfloat16* __restrict__ vth, __nv_bfloat16* __restrict__ vtl)
{
    __shared__ float t[32][33];
    const int tx = threadIdx.x & 31, ty = threadIdx.x >> 5;
    const int s0 = blockIdx.x * 32, d0 = blockIdx.y * 32, bh = blockIdx.z;
    const int b = bh >> 4, h = bh & 15;
    #pragma unroll
    for (int r = 0; r < 4; r++)
        t[ty + 8 * r][tx] = qkv[((size_t)(b * SL + s0 + ty + 8 * r)) * (3 * NE)
                                + 2 * NE + h * HD + d0 + tx];
    __syncthreads();
    #pragma unroll
    for (int r = 0; r < 4; r++) {
        float v = t[tx][ty + 8 * r];   // = V[s0+tx][d0+ty+8r]
        __nv_bfloat16 hh = __float2bfloat16(v);
        size_t o = ((size_t)bh * HD + d0 + ty + 8 * r) * SL + s0 + tx;
        vth[o] = hh;
        vtl[o] = __float2bfloat16(v - __bfloat162float(hh));
    }
}

// ---------------- HMMA bf16x3 GEMM (validated R5) ----------------
#define SROWB 80
#define TILEB (128 * SROWB)
#define STAGEB (4 * TILEB)
#define GEMM_SMEM (2 * STAGEB)

__global__ __launch_bounds__(256)
void gemm_bf16x3(const __nv_bfloat16* __restrict__ Ah, const __nv_bfloat16* __restrict__ Al,
                 const __nv_bfloat16* __restrict__ Bh, const __nv_bfloat16* __restrict__ Bl,
                 const float* __restrict__ bias, float* __restrict__ C, int N)
{
    extern __shared__ __align__(128) char smem[];
    const int tid = threadIdx.x;
    const int wid = tid >> 5;
    const int lane = tid & 31;
    const int bm = blockIdx.y * 128;
    const int bn = blockIdx.x * 128;
    const uint32_t sbase = smem_u32(smem);

    const int wm = wid & 1;
    const int wn = wid >> 1;

    float acc[4][4][4];
    #pragma unroll
    for (int mi = 0; mi < 4; mi++)
        #pragma unroll
        for (int ni = 0; ni < 4; ni++)
            #pragma unroll
            for (int e = 0; e < 4; e++) acc[mi][ni][e] = 0.f;

    auto load_chunk = [&](int c, int st) {
        const uint32_t sb = sbase + st * STAGEB;
        const __nv_bfloat16* srcs[4] = {Ah, Al, Bh, Bl};
        const int r0s[4] = {bm, bm, bn, bn};
        #pragma unroll
        for (int t = 0; t < 4; t++) {
            const char* G = (const char*)srcs[t];
            #pragma unroll
            for (int i = 0; i < 2; i++) {
                const int lin = tid + 256 * i;
                const int row = lin >> 2, g = lin & 3;
                const uint32_t dst = sb + t * TILEB + row * SROWB + g * 16;
                const char* src = G + (size_t)(r0s[t] + row) * (GK * 2)
                                    + (size_t)c * (BKC * 2) + g * 16;
                cp_async16(dst, src);
            }
        }
    };

    auto compute = [&](int st) {
        const uint32_t tAh = sbase + st * STAGEB;
        const uint32_t tAl = tAh + TILEB;
        const uint32_t tBh = tAh + 2 * TILEB;
        const uint32_t tBl = tAh + 3 * TILEB;
        #pragma unroll
        for (int ks = 0; ks < 2; ks++) {
            uint32_t fah[4][4], fal[4][4], fbh[4][2], fbl[4][2];
            #pragma unroll
            for (int mi = 0; mi < 4; mi++) {
                const int row = wm * 64 + mi * 16 + (lane & 15);
                const uint32_t off = row * SROWB + ks * 32 + (lane >> 4) * 16;
                ldmatrix_x4(fah[mi], tAh + off);
                ldmatrix_x4(fal[mi], tAl + off);
            }
            #pragma unroll
            for (int ni = 0; ni < 4; ni++) {
                const int nrow = wn * 32 + ni * 8 + (lane & 7);
                const uint32_t off = nrow * SROWB + ks * 32 + ((lane >> 3) & 1) * 16;
                ldmatrix_x2(fbh[ni], tBh + off);
                ldmatrix_x2(fbl[ni], tBl + off);
            }
            #pragma unroll
            for (int mi = 0; mi < 4; mi++)
                #pragma unroll
                for (int ni = 0; ni < 4; ni++) {
                    mma_bf16(acc[mi][ni], fah[mi], fbh[ni][0], fbh[ni][1]);
                    mma_bf16(acc[mi][ni], fah[mi], fbl[ni][0], fbl[ni][1]);
                    mma_bf16(acc[mi][ni], fal[mi], fbh[ni][0], fbh[ni][1]);
                }
        }
    };

    load_chunk(0, 0);
    cp_commit();
    for (int c = 0; c < NCH; c++) {
        const int s = c & 1;
        if (c + 1 < NCH) {
            load_chunk(c + 1, s ^ 1);
            cp_commit();
            asm volatile("cp.async.wait_group 1;" ::: "memory");
        } else {
            asm volatile("cp.async.wait_group 0;" ::: "memory");
        }
        __syncthreads();
        compute(s);
        __syncthreads();
    }

    #pragma unroll
    for (int mi = 0; mi < 4; mi++) {
        const int r0 = bm + wm * 64 + mi * 16 + (lane >> 2);
        #pragma unroll
        for (int ni = 0; ni < 4; ni++) {
            const int c0 = bn + wn * 32 + ni * 8 + (lane & 3) * 2;
            const float2 bv = *(const float2*)(bias + c0);
            float2 o0, o1;
            o0.x = acc[mi][ni][0] + bv.x;
            o0.y = acc[mi][ni][1] + bv.y;
            o1.x = acc[mi][ni][2] + bv.x;
            o1.y = acc[mi][ni][3] + bv.y;
            *(float2*)(C + (size_t)r0 * N + c0) = o0;
            *(float2*)(C + (size_t)(r0 + 8) * N + c0) = o1;
        }
    }
}

// ---------------- HMMA flash attention (bf16x3, causal) ----------------
// CTA: 128 q rows x 8 warps (16 rows each), KV tiles of 64, double-buffered.
// Rows are HD=64 bf16 = 128 bytes -> ASTR = 144 (128 data + 16 pad).
#define ABQ 128
#define ABK 64
#define ASTR 144
#define ATILEB (64 * ASTR)        // 9216
#define ASTAGEB (4 * ATILEB)      // 36864: Kh, Kl, Vth, Vtl
#define ATTN_SMEM (2 * ASTAGEB)   // 73728

__global__ __launch_bounds__(256) void attn_mma_kernel(
    const __nv_bfloat16* __restrict__ Qh, const __nv_bfloat16* __restrict__ Ql,
    const __nv_bfloat16* __restrict__ Kh, const __nv_bfloat16* __restrict__ Kl,
    const __nv_bfloat16* __restrict__ Vth, const __nv_bfloat16* __restrict__ Vtl,
    float* __restrict__ y)
{
    extern __shared__ __align__(128) char smem[];
    const int tid = threadIdx.x;
    const int wq = tid >> 5;
    const int lane = tid & 31;
    const int bh = blockIdx.y;
    const int b = bh >> 4, h = bh & 15;
    const int qt = gridDim.x - 1 - blockIdx.x;   // heavy tiles first
    const int q0 = qt * ABQ;
    const uint32_t sbase = smem_u32(smem);

    const __nv_bfloat16* Qhb = Qh + (size_t)bh * SL * HD;
    const __nv_bfloat16* Qlb = Ql + (size_t)bh * SL * HD;
    const __nv_bfloat16* Khb = Kh + (size_t)bh * SL * HD;
    const __nv_bfloat16* Klb = Kl + (size_t)bh * SL * HD;
    const __nv_bfloat16* Vthb = Vth + (size_t)bh * HD * SL;
    const __nv_bfloat16* Vtlb = Vtl + (size_t)bh * HD * SL;

    // ---- load Q tile (128 rows x 128B, hi/lo) into smem, extract A frags ----
    uint32_t qfh[4][4], qfl[4][4];
    {
        const uint32_t qlo = sbase + 128 * ASTR;   // lo tile after hi tile
        #pragma unroll
        for (int i = 0; i < 4; i++) {
            const int lin = tid + 256 * i;         // 0..1023
            const int row = lin >> 3, g = lin & 7;
            cp_async16(sbase + row * ASTR + g * 16,
                       Qhb + (size_t)(q0 + row) * HD + g * 8);
            cp_async16(qlo + row * ASTR + g * 16,
                       Qlb + (size_t)(q0 + row) * HD + g * 8);
        }
        cp_commit();
        asm volatile("cp.async.wait_group 0;" ::: "memory");
        __syncthreads();
        #pragma unroll
        for (int ks = 0; ks < 4; ks++) {
            const uint32_t off = (wq * 16 + (lane & 15)) * ASTR + ks * 32 + (lane >> 4) * 16;
            ldmatrix_x4(qfh[ks], sbase + off);
            ldmatrix_x4(qfl[ks], qlo + off);
        }
        __syncthreads();
    }

    // KV loader: 4 tiles (Kh, Kl, Vth, Vtl), each 64 rows x 128B
    auto load_kv = [&](int t, int st) {
        const uint32_t sb = sbase + st * ASTAGEB;
        const int k0 = t * ABK;
        #pragma unroll
        for (int i = 0; i < 2; i++) {
            const int lin = tid + 256 * i;         // 0..511
            const int row = lin >> 3, g = lin & 7;
            const uint32_t ro = row * ASTR + g * 16;
            cp_async16(sb + 0 * ATILEB + ro, Khb  + (size_t)(k0 + row) * HD + g * 8);
            cp_async16(sb + 1 * ATILEB + ro, Klb  + (size_t)(k0 + row) * HD + g * 8);
            cp_async16(sb + 2 * ATILEB + ro, Vthb + (size_t)row * SL + k0 + g * 8);
            cp_async16(sb + 3 * ATILEB + ro, Vtlb + (size_t)row * SL + k0 + g * 8);
        }
    };

    float o[8][4];
    #pragma unroll
    for (int j = 0; j < 8; j++)
        #pragma unroll
        for (int e = 0; e < 4; e++) o[j][e] = 0.f;
    float m0 = -1e30f, m1 = -1e30f, l0 = 0.f, l1 = 0.f;

    const int ntiles = 2 * qt + 2;
    load_kv(0, 0);
    cp_commit();

    for (int t = 0; t < ntiles; t++) {
        const int s = t & 1;
        if (t + 1 < ntiles) {
            load_kv(t + 1, s ^ 1);
            cp_commit();
            asm volatile("cp.async.wait_group 1;" ::: "memory");
        } else {
            asm volatile("cp.async.wait_group 0;" ::: "memory");
        }
        __syncthreads();
        const uint32_t sb = sbase + s * ASTAGEB;

        // ---- S = Qh.Kh + Ql.Kh + Qh.Kl ----
        float sacc[8][4];
        #pragma unroll
        for (int j = 0; j < 8; j++)
            #pragma unroll
            for (int e = 0; e < 4; e++) sacc[j][e] = 0.f;
        #pragma unroll
        for (int ks = 0; ks < 4; ks++) {
            #pragma unroll
            for (int nj = 0; nj < 4; nj++) {
                uint32_t fh[4], fl[4];
                const uint32_t off = (nj * 16 + (lane & 15)) * ASTR + ks * 32 + (lane >> 4) * 16;
                ldmatrix_x4(fh, sb + 0 * ATILEB + off);
                ldmatrix_x4(fl, sb + 1 * ATILEB + off);
                mma_bf16(sacc[2 * nj],     qfh[ks], fh[0], fh[2]);
                mma_bf16(sacc[2 * nj],     qfl[ks], fh[0], fh[2]);
                mma_bf16(sacc[2 * nj],     qfh[ks], fl[0], fl[2]);
                mma_bf16(sacc[2 * nj + 1], qfh[ks], fh[1], fh[3]);
                mma_bf16(sacc[2 * nj + 1], qfl[ks], fh[1], fh[3]);
                mma_bf16(sacc[2 * nj + 1], qfh[ks], fl[1], fl[3]);
            }
        }

        // ---- causal mask (only tiles crossing the diagonal) ----
        const int k0 = t * ABK;
        const int row0 = q0 + wq * 16 + (lane >> 2);
        if (k0 + ABK - 1 > q0 + wq * 16) {
            #pragma unroll
            for (int ni = 0; ni < 8; ni++) {
                const int c0 = k0 + ni * 8 + (lane & 3) * 2;
                if (c0 > row0)         sacc[ni][0] = -1e30f;
                if (c0 + 1 > row0)     sacc[ni][1] = -1e30f;
                if (c0 > row0 + 8)     sacc[ni][2] = -1e30f;
                if (c0 + 1 > row0 + 8) sacc[ni][3] = -1e30f;
            }
        }

        // ---- online softmax (rows r = lane>>2 and r+8) ----
        float mt0 = -1e30f, mt1 = -1e30f;
        #pragma unroll
        for (int ni = 0; ni < 8; ni++) {
            mt0 = fmaxf(mt0, fmaxf(sacc[ni][0], sacc[ni][1]));
            mt1 = fmaxf(mt1, fmaxf(sacc[ni][2], sacc[ni][3]));
        }
        mt0 = fmaxf(mt0, __shfl_xor_sync(0xFFFFFFFFu, mt0, 1));
        mt0 = fmaxf(mt0, __shfl_xor_sync(0xFFFFFFFFu, mt0, 2));
        mt1 = fmaxf(mt1, __shfl_xor_sync(0xFFFFFFFFu, mt1, 1));
        mt1 = fmaxf(mt1, __shfl_xor_sync(0xFFFFFFFFu, mt1, 2));
        const float mn0 = fmaxf(m0, mt0), mn1 = fmaxf(m1, mt1);
        const float cr0 = __expf(m0 - mn0), cr1 = __expf(m1 - mn1);
        float ps0 = 0.f, ps1 = 0.f;
        #pragma unroll
        for (int ni = 0; ni < 8; ni++) {
            sacc[ni][0] = __expf(sacc[ni][0] - mn0); ps0 += sacc[ni][0];
            sacc[ni][1] = __expf(sacc[ni][1] - mn0); ps0 += sacc[ni][1];
            sacc[ni][2] = __expf(sacc[ni][2] - mn1); ps1 += sacc[ni][2];
            sacc[ni][3] = __expf(sacc[ni][3] - mn1); ps1 += sacc[ni][3];
        }
        ps0 += __shfl_xor_sync(0xFFFFFFFFu, ps0, 1);
        ps0 += __shfl_xor_sync(0xFFFFFFFFu, ps0, 2);
        ps1 += __shfl_xor_sync(0xFFFFFFFFu, ps1, 1);
        ps1 += __shfl_xor_sync(0xFFFFFFFFu, ps1, 2);
        l0 = l0 * cr0 + ps0; l1 = l1 * cr1 + ps1;
        m0 = mn0; m1 = mn1;
        #pragma unroll
        for (int j = 0; j < 8; j++) {
            o[j][0] *= cr0; o[j][1] *= cr0;
            o[j][2] *= cr1; o[j][3] *= cr1;
        }

        // ---- pack P into A fragments (hi/lo), direct S->A layout mapping ----
        uint32_t pph[4][4], ppl[4][4];
        #pragma unroll
        for (int kt = 0; kt < 4; kt++) {
            split2(sacc[2 * kt][0],     sacc[2 * kt][1],     pph[kt][0], ppl[kt][0]);
            split2(sacc[2 * kt][2],     sacc[2 * kt][3],     pph[kt][1], ppl[kt][1]);
            split2(sacc[2 * kt + 1][0], sacc[2 * kt + 1][1], pph[kt][2], ppl[kt][2]);
            split2(sacc[2 * kt + 1][2], sacc[2 * kt + 1][3], pph[kt][3], ppl[kt][3]);
        }

        // ---- O += Ph.Vh + Pl.Vh + Ph.Vl ----
        #pragma unroll
        for (int kt = 0; kt < 4; kt++) {
            #pragma unroll
            for (int nj = 0; nj < 4; nj++) {
                uint32_t fh[4], fl[4];
                const uint32_t off = (nj * 16 + (lane & 15)) * ASTR + kt * 32 + (lane >> 4) * 16;
                ldmatrix_x4(fh, sb + 2 * ATILEB + off);
                ldmatrix_x4(fl, sb + 3 * ATILEB + off);
                mma_bf16(o[2 * nj],     pph[kt], fh[0], fh[2]);
                mma_bf16(o[2 * nj],     ppl[kt], fh[0], fh[2]);
                mma_bf16(o[2 * nj],     pph[kt], fl[0], fl[2]);
                mma_bf16(o[2 * nj + 1], pph[kt], fh[1], fh[3]);
                mma_bf16(o[2 * nj + 1], ppl[kt], fh[1], fh[3]);
                mma_bf16(o[2 * nj + 1], pph[kt], fl[1], fl[3]);
            }
        }
        __syncthreads();
    }

    // ---- epilogue: normalize + write y [b, s, ne] ----
    const float i0 = 1.f / l0, i1 = 1.f / l1;
    const int row = q0 + wq * 16 + (lane >> 2);
    float* d0 = y + ((size_t)(b * SL + row)) * NE + h * HD;
    float* d1 = d0 + (size_t)8 * NE;
    #pragma unroll
    for (int j = 0; j < 8; j++) {
        const int col = j * 8 + (lane & 3) * 2;
        float2 v0, v1;
        v0.x = o[j][0] * i0; v0.y = o[j][1] * i0;
        v1.x = o[j][2] * i1; v1.y = o[j][3] * i1;
        *(float2*)(d0 + col) = v0;
        *(float2*)(d1 + col) = v1;
    }
}

// ---------------- launch ----------------
extern "C" void kernel_launch(void* const* d_in, const int* in_sizes, int n_in,
                              void* d_out, int out_size)
{
    const float* x    = (const float*)d_in[0];
    const float* Wqkv = (const float*)d_in[2];
    const float* bqkv = (const float*)d_in[3];
    const float* Wo   = (const float*)d_in[4];
    const float* bo   = (const float*)d_in[5];
    float* out = (float*)d_out;

    float *qkv, *ybuf;
    __nv_bfloat16 *xh, *xl, *yh, *yl, *wqh, *wql, *woh, *wol;
    __nv_bfloat16 *aqh, *aql, *akh, *akl, *avth, *avtl;
    cudaGetSymbolAddress((void**)&qkv, g_qkv);
    cudaGetSymbolAddress((void**)&ybuf, g_y);
    cudaGetSymbolAddress((void**)&xh, g_xh);
    cudaGetSymbolAddress((void**)&xl, g_xl);
    cudaGetSymbolAddress((void**)&yh, g_yh);
    cudaGetSymbolAddress((void**)&yl, g_yl);
    cudaGetSymbolAddress((void**)&wqh, g_wqh);
    cudaGetSymbolAddress((void**)&wql, g_wql);
    cudaGetSymbolAddress((void**)&woh, g_woh);
    cudaGetSymbolAddress((void**)&wol, g_wol);
    cudaGetSymbolAddress((void**)&aqh, g_aqh);
    cudaGetSymbolAddress((void**)&aql, g_aql);
    cudaGetSymbolAddress((void**)&akh, g_akh);
    cudaGetSymbolAddress((void**)&akl, g_akl);
    cudaGetSymbolAddress((void**)&avth, g_avth);
    cudaGetSymbolAddress((void**)&avtl, g_avtl);

    cudaFuncSetAttribute(gemm_bf16x3, cudaFuncAttributeMaxDynamicSharedMemorySize, GEMM_SMEM);
    cudaFuncSetAttribute(attn_mma_kernel, cudaFuncAttributeMaxDynamicSharedMemorySize, ATTN_SMEM);

    // split inputs / weights
    split_kernel<<<(MROWS * NE / 4 + 255) / 256, 256>>>(x, xh, xl, MROWS * NE / 4);
    tsplit_kernel<<<dim3(3 * NE / 32, NE / 32), 256>>>(Wqkv, wqh, wql, NE, 3 * NE);
    tsplit_kernel<<<dim3(NE / 32, NE / 32), 256>>>(Wo, woh, wol, NE, NE);

    // 1) QKV projection (HMMA bf16x3)
    gemm_bf16x3<<<dim3(3 * NE / 128, MROWS / 128), 256, GEMM_SMEM>>>(
        xh, xl, wqh, wql, bqkv, qkv, 3 * NE);

    // 2) attention prep (split + reshape + V transpose)
    qk_prep<<<(BHN * SL * 16) / 256, 256>>>(qkv, aqh, aql, akh, akl);
    vt_prep<<<dim3(SL / 32, HD / 32, BHN), 256>>>(qkv, avth, avtl);

    // 3) causal flash attention (HMMA bf16x3)
    attn_mma_kernel<<<dim3(SL / ABQ, BHN), 256, ATTN_SMEM>>>(
        aqh, aql, akh, akl, avth, avtl, ybuf);

    // 4) output projection (HMMA bf16x3)
    split_kernel<<<(MROWS * NE / 4 + 255) / 256, 256>>>(ybuf, yh, yl, MROWS * NE / 4);
    gemm_bf16x3<<<dim3(NE / 128, MROWS / 128), 256, GEMM_SMEM>>>(
        yh, yl, woh, wol, bo, out, NE);
}

// round 9
// speedup vs baseline: 5.0746x; 2.1292x over previous
#include <cuda_runtime.h>
#include <cuda_fp16.h>
#include <cstdint>

// Problem constants
#define BS 4
#define SL 2048
#define NE 1024
#define NH 16
#define HD 64
#define MROWS (BS*SL)          // 8192
#define GK 1024                // K dim for both GEMMs
#define BKC 32                 // K per chunk (fp16 elems)
#define NCH (GK / BKC)         // 32 chunks

// ---------------- scratch (no allocs allowed) ----------------
__device__ float g_qkv[(size_t)MROWS * 3 * NE];   // [8192, 3072]
__device__ float g_y[(size_t)MROWS * NE];         // [8192, 1024]
__device__ __half g_xh[(size_t)MROWS * NE];
__device__ __half g_xl[(size_t)MROWS * NE];
__device__ __half g_yh[(size_t)MROWS * NE];
__device__ __half g_yl[(size_t)MROWS * NE];
__device__ __half g_wqh[(size_t)3 * NE * NE];     // [3072,1024] (transposed, plain)
__device__ __half g_woh[(size_t)NE * NE];         // [1024,1024] (transposed, plain)
// attention operands, per (b,h): Q hi/lo + K plain [SL, HD], Vt plain [HD, SL]
#define BHN (BS * NH)   // 64
__device__ __half g_aqh[(size_t)BHN * SL * HD];
__device__ __half g_aql[(size_t)BHN * SL * HD];
__device__ __half g_akh[(size_t)BHN * SL * HD];
__device__ __half g_avth[(size_t)BHN * HD * SL];

// ---------------- helpers ----------------
__device__ __forceinline__ uint32_t smem_u32(const void* p) {
    uint32_t a;
    asm("{ .reg .u64 t; cvta.to.shared.u64 t, %1; cvt.u32.u64 %0, t; }" : "=r"(a) : "l"(p));
    return a;
}
__device__ __forceinline__ void cp_async16(uint32_t dst, const void* src) {
    asm volatile("cp.async.cg.shared.global [%0], [%1], 16;" :: "r"(dst), "l"(src) : "memory");
}
__device__ __forceinline__ void cp_commit() {
    asm volatile("cp.async.commit_group;" ::: "memory");
}
__device__ __forceinline__ void ldmatrix_x4(uint32_t* r, uint32_t addr) {
    asm volatile("ldmatrix.sync.aligned.m8n8.x4.shared.b16 {%0,%1,%2,%3}, [%4];"
                 : "=r"(r[0]), "=r"(r[1]), "=r"(r[2]), "=r"(r[3]) : "r"(addr));
}
__device__ __forceinline__ void ldmatrix_x2(uint32_t* r, uint32_t addr) {
    asm volatile("ldmatrix.sync.aligned.m8n8.x2.shared.b16 {%0,%1}, [%2];"
                 : "=r"(r[0]), "=r"(r[1]) : "r"(addr));
}
__device__ __forceinline__ void mma_f16(float* c, const uint32_t* a, uint32_t b0, uint32_t b1) {
    asm volatile(
        "mma.sync.aligned.m16n8k16.row.col.f32.f16.f16.f32 "
        "{%0,%1,%2,%3}, {%4,%5,%6,%7}, {%8,%9}, {%0,%1,%2,%3};"
        : "+f"(c[0]), "+f"(c[1]), "+f"(c[2]), "+f"(c[3])
        : "r"(a[0]), "r"(a[1]), "r"(a[2]), "r"(a[3]), "r"(b0), "r"(b1));
}
// split pair of floats into hi/lo fp16x2 packed regs
__device__ __forceinline__ void split2h(float a, float b, uint32_t& hi, uint32_t& lo) {
    __half2 h2 = __floats2half2_rn(a, b);
    hi = *reinterpret_cast<uint32_t*>(&h2);
    __half2 l2 = __floats2half2_rn(a - __half2float(h2.x), b - __half2float(h2.y));
    lo = *reinterpret_cast<uint32_t*>(&l2);
}

// ---------------- split / prep kernels ----------------
__global__ __launch_bounds__(256) void split_kernel(
    const float* __restrict__ in, __half* __restrict__ hi,
    __half* __restrict__ lo, int n4)
{
    int i = blockIdx.x * 256 + threadIdx.x;
    if (i >= n4) return;
    float4 v = ((const float4*)in)[i];
    uint32_t h0, l0, h1, l1;
    split2h(v.x, v.y, h0, l0);
    split2h(v.z, v.w, h1, l1);
    uint32_t* H = (uint32_t*)hi;
    uint32_t* L = (uint32_t*)lo;
    H[2 * i + 0] = h0; H[2 * i + 1] = h1;
    L[2 * i + 0] = l0; L[2 * i + 1] = l1;
}

// transpose (plain fp16): W [Kd, Nd] fp32 -> Wt [Nd, Kd] fp16
__global__ __launch_bounds__(256) void tsplit_kernel(
    const float* __restrict__ W, __half* __restrict__ hi, int Kd, int Nd)
{
    __shared__ float t[32][33];
    const int tx = threadIdx.x & 31, ty = threadIdx.x >> 5;  // 32 x 8
    const int k0 = blockIdx.y * 32, n0 = blockIdx.x * 32;
    #pragma unroll
    for (int r = 0; r < 4; r++)
        t[ty + 8 * r][tx] = W[(size_t)(k0 + ty + 8 * r) * Nd + n0 + tx];
    __syncthreads();
    #pragma unroll
    for (int r = 0; r < 4; r++)
        hi[(size_t)(n0 + ty + 8 * r) * Kd + k0 + tx] = __float2half(t[tx][ty + 8 * r]);
}

// Q (scaled by 1/8, split hi/lo) and K (plain): [bh][s][d]
__global__ __launch_bounds__(256) void qk_prep(
    const float* __restrict__ qkv,
    __half* __restrict__ qh, __half* __restrict__ ql, __half* __restrict__ kh)
{
    const int idx = blockIdx.x * 256 + threadIdx.x;   // BHN*SL*16
    const int dg = idx & 15;
    const int s  = (idx >> 4) & (SL - 1);
    const int bh = idx >> 15;
    const int b = bh >> 4, h = bh & 15;
    const float* src = qkv + ((size_t)(b * SL + s)) * (3 * NE) + h * HD + dg * 4;
    float4 q = *(const float4*)src;
    float4 k = *(const float4*)(src + NE);
    q.x *= 0.125f; q.y *= 0.125f; q.z *= 0.125f; q.w *= 0.125f;
    const size_t o = (((size_t)bh * SL + s) * HD + dg * 4) / 2;  // fp16x2 index
    uint32_t* QH = (uint32_t*)qh; uint32_t* QL = (uint32_t*)ql; uint32_t* KH = (uint32_t*)kh;
    uint32_t h0, l0, h1, l1;
    split2h(q.x, q.y, h0, l0); split2h(q.z, q.w, h1, l1);
    QH[o] = h0; QH[o + 1] = h1;
    QL[o] = l0; QL[o + 1] = l1;
    __half2 k0 = __floats2half2_rn(k.x, k.y), k1 = __floats2half2_rn(k.z, k.w);
    KH[o] = *(uint32_t*)&k0; KH[o + 1] = *(uint32_t*)&k1;
}

// V transpose (plain fp16): Vt[bh][d][s]
__global__ __launch_bounds__(256) void vt_prep(
    const float* __restrict__ qkv, __half* __restrict__ vth)
{
    __shared__ float t[32][33];
    const int tx = threadIdx.x & 31, ty = threadIdx.x >> 5;
    const int s0 = blockIdx.x * 32, d0 = blockIdx.y * 32, bh = blockIdx.z;
    const int b = bh >> 4, h = bh & 15;
    #pragma unroll
    for (int r = 0; r < 4; r++)
        t[ty + 8 * r][tx] = qkv[((size_t)(b * SL + s0 + ty + 8 * r)) * (3 * NE)
                                + 2 * NE + h * HD + d0 + tx];
    __syncthreads();
    #pragma unroll
    for (int r = 0; r < 4; r++)
        vth[((size_t)bh * HD + d0 + ty + 8 * r) * SL + s0 + tx] =
            __float2half(t[tx][ty + 8 * r]);
}

// ---------------- HMMA fp16x2 GEMM ----------------
// C[M,N] = A@B + bias. A hi/lo [M,GK] fp16, B plain [N,GK] fp16 (row = out col).
// CTA 128x128, K chunks of 32, cp.async double buffer, mma.sync m16n8k16.
#define SROWB 80                       // 64B data + 16B pad
#define TILEB (128 * SROWB)            // 10240
#define STAGEB (3 * TILEB)             // Ah, Al, Bh = 30720
#define GEMM_SMEM (2 * STAGEB)         // 61440

__global__ __launch_bounds__(256)
void gemm_f16x2(const __half* __restrict__ Ah, const __half* __restrict__ Al,
                const __half* __restrict__ Bh,
                const float* __restrict__ bias, float* __restrict__ C, int N)
{
    extern __shared__ __align__(128) char smem[];
    const int tid = threadIdx.x;
    const int wid = tid >> 5;
    const int lane = tid & 31;
    const int bm = blockIdx.y * 128;
    const int bn = blockIdx.x * 128;
    const uint32_t sbase = smem_u32(smem);

    const int wm = wid & 1;
    const int wn = wid >> 1;

    float acc[4][4][4];
    #pragma unroll
    for (int mi = 0; mi < 4; mi++)
        #pragma unroll
        for (int ni = 0; ni < 4; ni++)
            #pragma unroll
            for (int e = 0; e < 4; e++) acc[mi][ni][e] = 0.f;

    auto load_chunk = [&](int c, int st) {
        const uint32_t sb = sbase + st * STAGEB;
        const __half* srcs[3] = {Ah, Al, Bh};
        const int r0s[3] = {bm, bm, bn};
        #pragma unroll
        for (int t = 0; t < 3; t++) {
            const char* G = (const char*)srcs[t];
            #pragma unroll
            for (int i = 0; i < 2; i++) {
                const int lin = tid + 256 * i;
                const int row = lin >> 2, g = lin & 3;
                const uint32_t dst = sb + t * TILEB + row * SROWB + g * 16;
                const char* src = G + (size_t)(r0s[t] + row) * (GK * 2)
                                    + (size_t)c * (BKC * 2) + g * 16;
                cp_async16(dst, src);
            }
        }
    };

    auto compute = [&](int st) {
        const uint32_t tAh = sbase + st * STAGEB;
        const uint32_t tAl = tAh + TILEB;
        const uint32_t tBh = tAh + 2 * TILEB;
        #pragma unroll
        for (int ks = 0; ks < 2; ks++) {
            uint32_t fah[4][4], fal[4][4], fb[4][2];
            #pragma unroll
            for (int mi = 0; mi < 4; mi++) {
                const int row = wm * 64 + mi * 16 + (lane & 15);
                const uint32_t off = row * SROWB + ks * 32 + (lane >> 4) * 16;
                ldmatrix_x4(fah[mi], tAh + off);
                ldmatrix_x4(fal[mi], tAl + off);
            }
            #pragma unroll
            for (int ni = 0; ni < 4; ni++) {
                const int nrow = wn * 32 + ni * 8 + (lane & 7);
                const uint32_t off = nrow * SROWB + ks * 32 + ((lane >> 3) & 1) * 16;
                ldmatrix_x2(fb[ni], tBh + off);
            }
            #pragma unroll
            for (int mi = 0; mi < 4; mi++)
                #pragma unroll
                for (int ni = 0; ni < 4; ni++) {
                    mma_f16(acc[mi][ni], fah[mi], fb[ni][0], fb[ni][1]);
                    mma_f16(acc[mi][ni], fal[mi], fb[ni][0], fb[ni][1]);
                }
        }
    };

    load_chunk(0, 0);
    cp_commit();
    for (int c = 0; c < NCH; c++) {
        const int s = c & 1;
        if (c + 1 < NCH) {
            load_chunk(c + 1, s ^ 1);
            cp_commit();
            asm volatile("cp.async.wait_group 1;" ::: "memory");
        } else {
            asm volatile("cp.async.wait_group 0;" ::: "memory");
        }
        __syncthreads();
        compute(s);
        __syncthreads();
    }

    #pragma unroll
    for (int mi = 0; mi < 4; mi++) {
        const int r0 = bm + wm * 64 + mi * 16 + (lane >> 2);
        #pragma unroll
        for (int ni = 0; ni < 4; ni++) {
            const int c0 = bn + wn * 32 + ni * 8 + (lane & 3) * 2;
            const float2 bv = *(const float2*)(bias + c0);
            float2 o0, o1;
            o0.x = acc[mi][ni][0] + bv.x;
            o0.y = acc[mi][ni][1] + bv.y;
            o1.x = acc[mi][ni][2] + bv.x;
            o1.y = acc[mi][ni][3] + bv.y;
            *(float2*)(C + (size_t)r0 * N + c0) = o0;
            *(float2*)(C + (size_t)(r0 + 8) * N + c0) = o1;
        }
    }
}

// ---------------- HMMA flash attention (fp16x2, causal) ----------------
// CTA: 128 q rows x 8 warps, KV tiles of 64, double-buffered static smem.
// Rows are HD=64 fp16 = 128 bytes -> ASTR = 144 (128 data + 16 pad).
#define ABQ 128
#define ABK 64
#define ASTR 144
#define ATILEB (64 * ASTR)        // 9216
#define ASTAGEB (2 * ATILEB)      // 18432: Kh, Vth
#define ATTN_SMEM (2 * ASTAGEB)   // 36864 (also holds Q hi/lo during prologue)

__global__ __launch_bounds__(256) void attn_mma_kernel(
    const __half* __restrict__ Qh, const __half* __restrict__ Ql,
    const __half* __restrict__ Kh, const __half* __restrict__ Vth,
    float* __restrict__ y)
{
    __shared__ __align__(128) char smem[ATTN_SMEM];
    const int tid = threadIdx.x;
    const int wq = tid >> 5;
    const int lane = tid & 31;
    const int bh = blockIdx.y;
    const int b = bh >> 4, h = bh & 15;
    const int qt = gridDim.x - 1 - blockIdx.x;   // heavy tiles first
    const int q0 = qt * ABQ;
    const uint32_t sbase = smem_u32(smem);

    const __half* Qhb = Qh + (size_t)bh * SL * HD;
    const __half* Qlb = Ql + (size_t)bh * SL * HD;
    const __half* Khb = Kh + (size_t)bh * SL * HD;
    const __half* Vthb = Vth + (size_t)bh * HD * SL;

    // ---- load Q tile (128 rows x 128B, hi/lo) into smem, extract A frags ----
    uint32_t qfh[4][4], qfl[4][4];
    {
        const uint32_t qlo = sbase + 128 * ASTR;   // 18432
        #pragma unroll
        for (int i = 0; i < 4; i++) {
            const int lin = tid + 256 * i;         // 0..1023
            const int row = lin >> 3, g = lin & 7;
            cp_async16(sbase + row * ASTR + g * 16,
                       Qhb + (size_t)(q0 + row) * HD + g * 8);
            cp_async16(qlo + row * ASTR + g * 16,
                       Qlb + (size_t)(q0 + row) * HD + g * 8);
        }
        cp_commit();
        asm volatile("cp.async.wait_group 0;" ::: "memory");
        __syncthreads();
        #pragma unroll
        for (int ks = 0; ks < 4; ks++) {
            const uint32_t off = (wq * 16 + (lane & 15)) * ASTR + ks * 32 + (lane >> 4) * 16;
            ldmatrix_x4(qfh[ks], sbase + off);
            ldmatrix_x4(qfl[ks], qlo + off);
        }
        __syncthreads();
    }

    // KV loader: 2 tiles (Kh, Vth), each 64 rows x 128B
    auto load_kv = [&](int t, int st) {
        const uint32_t sb = sbase + st * ASTAGEB;
        const int k0 = t * ABK;
        #pragma unroll
        for (int i = 0; i < 2; i++) {
            const int lin = tid + 256 * i;         // 0..511
            const int row = lin >> 3, g = lin & 7;
            const uint32_t ro = row * ASTR + g * 16;
            cp_async16(sb + 0 * ATILEB + ro, Khb  + (size_t)(k0 + row) * HD + g * 8);
            cp_async16(sb + 1 * ATILEB + ro, Vthb + (size_t)row * SL + k0 + g * 8);
        }
    };

    float o[8][4];
    #pragma unroll
    for (int j = 0; j < 8; j++)
        #pragma unroll
        for (int e = 0; e < 4; e++) o[j][e] = 0.f;
    float m0 = -1e30f, m1 = -1e30f, l0 = 0.f, l1 = 0.f;

    const int ntiles = 2 * qt + 2;
    load_kv(0, 0);
    cp_commit();

    for (int t = 0; t < ntiles; t++) {
        const int s = t & 1;
        if (t + 1 < ntiles) {
            load_kv(t + 1, s ^ 1);
            cp_commit();
            asm volatile("cp.async.wait_group 1;" ::: "memory");
        } else {
            asm volatile("cp.async.wait_group 0;" ::: "memory");
        }
        __syncthreads();
        const uint32_t sb = sbase + s * ASTAGEB;

        // ---- S = Qh.K + Ql.K ----
        float sacc[8][4];
        #pragma unroll
        for (int j = 0; j < 8; j++)
            #pragma unroll
            for (int e = 0; e < 4; e++) sacc[j][e] = 0.f;
        #pragma unroll
        for (int ks = 0; ks < 4; ks++) {
            #pragma unroll
            for (int nj = 0; nj < 4; nj++) {
                uint32_t fh[4];
                const uint32_t off = (nj * 16 + (lane & 15)) * ASTR + ks * 32 + (lane >> 4) * 16;
                ldmatrix_x4(fh, sb + off);
                mma_f16(sacc[2 * nj],     qfh[ks], fh[0], fh[2]);
                mma_f16(sacc[2 * nj],     qfl[ks], fh[0], fh[2]);
                mma_f16(sacc[2 * nj + 1], qfh[ks], fh[1], fh[3]);
                mma_f16(sacc[2 * nj + 1], qfl[ks], fh[1], fh[3]);
            }
        }

        // ---- causal mask (only tiles crossing the diagonal) ----
        const int k0 = t * ABK;
        const int row0 = q0 + wq * 16 + (lane >> 2);
        if (k0 + ABK - 1 > q0 + wq * 16) {
            #pragma unroll
            for (int ni = 0; ni < 8; ni++) {
                const int c0 = k0 + ni * 8 + (lane & 3) * 2;
                if (c0 > row0)         sacc[ni][0] = -1e30f;
                if (c0 + 1 > row0)     sacc[ni][1] = -1e30f;
                if (c0 > row0 + 8)     sacc[ni][2] = -1e30f;
                if (c0 + 1 > row0 + 8) sacc[ni][3] = -1e30f;
            }
        }

        // ---- online softmax (rows r = lane>>2 and r+8) ----
        float mt0 = -1e30f, mt1 = -1e30f;
        #pragma unroll
        for (int ni = 0; ni < 8; ni++) {
            mt0 = fmaxf(mt0, fmaxf(sacc[ni][0], sacc[ni][1]));
            mt1 = fmaxf(mt1, fmaxf(sacc[ni][2], sacc[ni][3]));
        }
        mt0 = fmaxf(mt0, __shfl_xor_sync(0xFFFFFFFFu, mt0, 1));
        mt0 = fmaxf(mt0, __shfl_xor_sync(0xFFFFFFFFu, mt0, 2));
        mt1 = fmaxf(mt1, __shfl_xor_sync(0xFFFFFFFFu, mt1, 1));
        mt1 = fmaxf(mt1, __shfl_xor_sync(0xFFFFFFFFu, mt1, 2));
        const float mn0 = fmaxf(m0, mt0), mn1 = fmaxf(m1, mt1);
        const float cr0 = __expf(m0 - mn0), cr1 = __expf(m1 - mn1);
        float ps0 = 0.f, ps1 = 0.f;
        #pragma unroll
        for (int ni = 0; ni < 8; ni++) {
            sacc[ni][0] = __expf(sacc[ni][0] - mn0); ps0 += sacc[ni][0];
            sacc[ni][1] = __expf(sacc[ni][1] - mn0); ps0 += sacc[ni][1];
            sacc[ni][2] = __expf(sacc[ni][2] - mn1); ps1 += sacc[ni][2];
            sacc[ni][3] = __expf(sacc[ni][3] - mn1); ps1 += sacc[ni][3];
        }
        ps0 += __shfl_xor_sync(0xFFFFFFFFu, ps0, 1);
        ps0 += __shfl_xor_sync(0xFFFFFFFFu, ps0, 2);
        ps1 += __shfl_xor_sync(0xFFFFFFFFu, ps1, 1);
        ps1 += __shfl_xor_sync(0xFFFFFFFFu, ps1, 2);
        l0 = l0 * cr0 + ps0; l1 = l1 * cr1 + ps1;
        m0 = mn0; m1 = mn1;
        #pragma unroll
        for (int j = 0; j < 8; j++) {
            o[j][0] *= cr0; o[j][1] *= cr0;
            o[j][2] *= cr1; o[j][3] *= cr1;
        }

        // ---- pack P into A fragments (hi/lo fp16), direct S->A layout ----
        uint32_t pph[4][4], ppl[4][4];
        #pragma unroll
        for (int kt = 0; kt < 4; kt++) {
            split2h(sacc[2 * kt][0],     sacc[2 * kt][1],     pph[kt][0], ppl[kt][0]);
            split2h(sacc[2 * kt][2],     sacc[2 * kt][3],     pph[kt][1], ppl[kt][1]);
            split2h(sacc[2 * kt + 1][0], sacc[2 * kt + 1][1], pph[kt][2], ppl[kt][2]);
            split2h(sacc[2 * kt + 1][2], sacc[2 * kt + 1][3], pph[kt][3], ppl[kt][3]);
        }

        // ---- O += Ph.V + Pl.V ----
        #pragma unroll
        for (int kt = 0; kt < 4; kt++) {
            #pragma unroll
            for (int nj = 0; nj < 4; nj++) {
                uint32_t fh[4];
                const uint32_t off = (nj * 16 + (lane & 15)) * ASTR + kt * 32 + (lane >> 4) * 16;
                ldmatrix_x4(fh, sb + ATILEB + off);
                mma_f16(o[2 * nj],     pph[kt], fh[0], fh[2]);
                mma_f16(o[2 * nj],     ppl[kt], fh[0], fh[2]);
                mma_f16(o[2 * nj + 1], pph[kt], fh[1], fh[3]);
                mma_f16(o[2 * nj + 1], ppl[kt], fh[1], fh[3]);
            }
        }
        __syncthreads();
    }

    // ---- epilogue: normalize + write y [b, s, ne] ----
    const float i0 = 1.f / l0, i1 = 1.f / l1;
    const int row = q0 + wq * 16 + (lane >> 2);
    float* d0 = y + ((size_t)(b * SL + row)) * NE + h * HD;
    float* d1 = d0 + (size_t)8 * NE;
    #pragma unroll
    for (int j = 0; j < 8; j++) {
        const int col = j * 8 + (lane & 3) * 2;
        float2 v0, v1;
        v0.x = o[j][0] * i0; v0.y = o[j][1] * i0;
        v1.x = o[j][2] * i1; v1.y = o[j][3] * i1;
        *(float2*)(d0 + col) = v0;
        *(float2*)(d1 + col) = v1;
    }
}

// ---------------- launch ----------------
extern "C" void kernel_launch(void* const* d_in, const int* in_sizes, int n_in,
                              void* d_out, int out_size)
{
    const float* x    = (const float*)d_in[0];
    const float* Wqkv = (const float*)d_in[2];
    const float* bqkv = (const float*)d_in[3];
    const float* Wo   = (const float*)d_in[4];
    const float* bo   = (const float*)d_in[5];
    float* out = (float*)d_out;

    float *qkv, *ybuf;
    __half *xh, *xl, *yh, *yl, *wqh, *woh;
    __half *aqh, *aql, *akh, *avth;
    cudaGetSymbolAddress((void**)&qkv, g_qkv);
    cudaGetSymbolAddress((void**)&ybuf, g_y);
    cudaGetSymbolAddress((void**)&xh, g_xh);
    cudaGetSymbolAddress((void**)&xl, g_xl);
    cudaGetSymbolAddress((void**)&yh, g_yh);
    cudaGetSymbolAddress((void**)&yl, g_yl);
    cudaGetSymbolAddress((void**)&wqh, g_wqh);
    cudaGetSymbolAddress((void**)&woh, g_woh);
    cudaGetSymbolAddress((void**)&aqh, g_aqh);
    cudaGetSymbolAddress((void**)&aql, g_aql);
    cudaGetSymbolAddress((void**)&akh, g_akh);
    cudaGetSymbolAddress((void**)&avth, g_avth);

    cudaFuncSetAttribute(gemm_f16x2, cudaFuncAttributeMaxDynamicSharedMemorySize, GEMM_SMEM);

    // split inputs / weights
    split_kernel<<<(MROWS * NE / 4 + 255) / 256, 256>>>(x, xh, xl, MROWS * NE / 4);
    tsplit_kernel<<<dim3(3 * NE / 32, NE / 32), 256>>>(Wqkv, wqh, NE, 3 * NE);
    tsplit_kernel<<<dim3(NE / 32, NE / 32), 256>>>(Wo, woh, NE, NE);

    // 1) QKV projection (HMMA fp16x2)
    gemm_f16x2<<<dim3(3 * NE / 128, MROWS / 128), 256, GEMM_SMEM>>>(
        xh, xl, wqh, bqkv, qkv, 3 * NE);

    // 2) attention prep (split + reshape + V transpose)
    qk_prep<<<(BHN * SL * 16) / 256, 256>>>(qkv, aqh, aql, akh);
    vt_prep<<<dim3(SL / 32, HD / 32, BHN), 256>>>(qkv, avth);

    // 3) causal flash attention (HMMA fp16x2)
    attn_mma_kernel<<<dim3(SL / ABQ, BHN), 256>>>(aqh, aql, akh, avth, ybuf);

    // 4) output projection (HMMA fp16x2)
    split_kernel<<<(MROWS * NE / 4 + 255) / 256, 256>>>(ybuf, yh, yl, MROWS * NE / 4);
    gemm_f16x2<<<dim3(NE / 128, MROWS / 128), 256, GEMM_SMEM>>>(
        yh, yl, woh, bo, out, NE);
}

// round 10
// speedup vs baseline: 5.5322x; 1.0902x over previous
#include <cuda_runtime.h>
#include <cuda_fp16.h>
#include <cstdint>

// Problem constants
#define BS 4
#define SL 2048
#define NE 1024
#define NH 16
#define HD 64
#define MROWS (BS*SL)          // 8192
#define GK 1024                // K dim for both GEMMs
#define BKC 32                 // K per chunk (fp16 elems)
#define NCH (GK / BKC)         // 32 chunks
#define BHN (BS * NH)          // 64

// ---------------- scratch (no allocs allowed) ----------------
__device__ __half g_xh[(size_t)MROWS * NE];
__device__ __half g_xl[(size_t)MROWS * NE];
__device__ __half g_yh[(size_t)MROWS * NE];
__device__ __half g_yl[(size_t)MROWS * NE];
__device__ __half g_wqh[(size_t)3 * NE * NE];     // [3072,1024] (transposed)
__device__ __half g_woh[(size_t)NE * NE];         // [1024,1024] (transposed)
// attention operands, per (b,h)
__device__ __half g_aqh[(size_t)BHN * SL * HD];
__device__ __half g_aql[(size_t)BHN * SL * HD];
__device__ __half g_akh[(size_t)BHN * SL * HD];
__device__ __half g_avf[(size_t)BHN * SL * HD];   // V fp16 [bh][s][d]
__device__ __half g_avth[(size_t)BHN * HD * SL];  // V^T [bh][d][s]

// ---------------- helpers ----------------
__device__ __forceinline__ uint32_t smem_u32(const void* p) {
    uint32_t a;
    asm("{ .reg .u64 t; cvta.to.shared.u64 t, %1; cvt.u32.u64 %0, t; }" : "=r"(a) : "l"(p));
    return a;
}
__device__ __forceinline__ void cp_async16(uint32_t dst, const void* src) {
    asm volatile("cp.async.cg.shared.global [%0], [%1], 16;" :: "r"(dst), "l"(src) : "memory");
}
__device__ __forceinline__ void cp_commit() {
    asm volatile("cp.async.commit_group;" ::: "memory");
}
template<int N> __device__ __forceinline__ void cp_wait() {
    asm volatile("cp.async.wait_group %0;" :: "n"(N) : "memory");
}
__device__ __forceinline__ void ldmatrix_x4(uint32_t* r, uint32_t addr) {
    asm volatile("ldmatrix.sync.aligned.m8n8.x4.shared.b16 {%0,%1,%2,%3}, [%4];"
                 : "=r"(r[0]), "=r"(r[1]), "=r"(r[2]), "=r"(r[3]) : "r"(addr));
}
__device__ __forceinline__ void ldmatrix_x2(uint32_t* r, uint32_t addr) {
    asm volatile("ldmatrix.sync.aligned.m8n8.x2.shared.b16 {%0,%1}, [%2];"
                 : "=r"(r[0]), "=r"(r[1]) : "r"(addr));
}
__device__ __forceinline__ void mma_f16(float* c, const uint32_t* a, uint32_t b0, uint32_t b1) {
    asm volatile(
        "mma.sync.aligned.m16n8k16.row.col.f32.f16.f16.f32 "
        "{%0,%1,%2,%3}, {%4,%5,%6,%7}, {%8,%9}, {%0,%1,%2,%3};"
        : "+f"(c[0]), "+f"(c[1]), "+f"(c[2]), "+f"(c[3])
        : "r"(a[0]), "r"(a[1]), "r"(a[2]), "r"(a[3]), "r"(b0), "r"(b1));
}
__device__ __forceinline__ void split2h(float a, float b, uint32_t& hi, uint32_t& lo) {
    __half2 h2 = __floats2half2_rn(a, b);
    hi = *reinterpret_cast<uint32_t*>(&h2);
    __half2 l2 = __floats2half2_rn(a - __half2float(h2.x), b - __half2float(h2.y));
    lo = *reinterpret_cast<uint32_t*>(&l2);
}
__device__ __forceinline__ uint32_t pack2h(float a, float b) {
    __half2 h2 = __floats2half2_rn(a, b);
    return *reinterpret_cast<uint32_t*>(&h2);
}

// ---------------- split / prep kernels ----------------
__global__ __launch_bounds__(256) void split_kernel(
    const float* __restrict__ in, __half* __restrict__ hi,
    __half* __restrict__ lo, int n4)
{
    int i = blockIdx.x * 256 + threadIdx.x;
    if (i >= n4) return;
    float4 v = ((const float4*)in)[i];
    uint32_t h0, l0, h1, l1;
    split2h(v.x, v.y, h0, l0);
    split2h(v.z, v.w, h1, l1);
    uint32_t* H = (uint32_t*)hi;
    uint32_t* L = (uint32_t*)lo;
    H[2 * i + 0] = h0; H[2 * i + 1] = h1;
    L[2 * i + 0] = l0; L[2 * i + 1] = l1;
}

// transpose (plain fp16): W [Kd, Nd] fp32 -> Wt [Nd, Kd] fp16
__global__ __launch_bounds__(256) void tsplit_kernel(
    const float* __restrict__ W, __half* __restrict__ hi, int Kd, int Nd)
{
    __shared__ float t[32][33];
    const int tx = threadIdx.x & 31, ty = threadIdx.x >> 5;  // 32 x 8
    const int k0 = blockIdx.y * 32, n0 = blockIdx.x * 32;
    #pragma unroll
    for (int r = 0; r < 4; r++)
        t[ty + 8 * r][tx] = W[(size_t)(k0 + ty + 8 * r) * Nd + n0 + tx];
    __syncthreads();
    #pragma unroll
    for (int r = 0; r < 4; r++)
        hi[(size_t)(n0 + ty + 8 * r) * Kd + k0 + tx] = __float2half(t[tx][ty + 8 * r]);
}

// V transpose (fp16): Vf [bh][s][d] -> Vt [bh][d][s]
__global__ __launch_bounds__(256) void vt_prep(
    const __half* __restrict__ vf, __half* __restrict__ vth)
{
    __shared__ float t[32][33];
    const int tx = threadIdx.x & 31, ty = threadIdx.x >> 5;
    const int s0 = blockIdx.x * 32, d0 = blockIdx.y * 32, bh = blockIdx.z;
    #pragma unroll
    for (int r = 0; r < 4; r++)
        t[ty + 8 * r][tx] = __half2float(
            vf[((size_t)bh * SL + s0 + ty + 8 * r) * HD + d0 + tx]);
    __syncthreads();
    #pragma unroll
    for (int r = 0; r < 4; r++)
        vth[((size_t)bh * HD + d0 + ty + 8 * r) * SL + s0 + tx] =
            __float2half(t[tx][ty + 8 * r]);
}

// ---------------- HMMA fp16x2 GEMM, 3-stage pipeline ----------------
// mode 0: C = A@B + bias (float out). mode 1: QKV fused epilogue.
#define SROWB 80                       // 64B data + 16B pad
#define TILEB (128 * SROWB)            // 10240
#define STAGEB (3 * TILEB)             // Ah, Al, Bh = 30720
#define GEMM_SMEM (3 * STAGEB)         // 92160

__global__ __launch_bounds__(256)
void gemm_f16x2(const __half* __restrict__ Ah, const __half* __restrict__ Al,
                const __half* __restrict__ Bh,
                const float* __restrict__ bias, float* __restrict__ C, int N,
                int mode, __half* __restrict__ qh, __half* __restrict__ ql,
                __half* __restrict__ kh, __half* __restrict__ vf)
{
    extern __shared__ __align__(128) char smem[];
    const int tid = threadIdx.x;
    const int wid = tid >> 5;
    const int lane = tid & 31;
    const int bm = blockIdx.y * 128;
    const int bn = blockIdx.x * 128;
    const uint32_t sbase = smem_u32(smem);

    const int wm = wid & 1;
    const int wn = wid >> 1;

    float acc[4][4][4];
    #pragma unroll
    for (int mi = 0; mi < 4; mi++)
        #pragma unroll
        for (int ni = 0; ni < 4; ni++)
            #pragma unroll
            for (int e = 0; e < 4; e++) acc[mi][ni][e] = 0.f;

    auto load_chunk = [&](int c, int st) {
        const uint32_t sb = sbase + st * STAGEB;
        const __half* srcs[3] = {Ah, Al, Bh};
        const int r0s[3] = {bm, bm, bn};
        #pragma unroll
        for (int t = 0; t < 3; t++) {
            const char* G = (const char*)srcs[t];
            #pragma unroll
            for (int i = 0; i < 2; i++) {
                const int lin = tid + 256 * i;
                const int row = lin >> 2, g = lin & 3;
                const uint32_t dst = sb + t * TILEB + row * SROWB + g * 16;
                const char* src = G + (size_t)(r0s[t] + row) * (GK * 2)
                                    + (size_t)c * (BKC * 2) + g * 16;
                cp_async16(dst, src);
            }
        }
        cp_commit();
    };

    auto compute = [&](int st) {
        const uint32_t tAh = sbase + st * STAGEB;
        const uint32_t tAl = tAh + TILEB;
        const uint32_t tBh = tAh + 2 * TILEB;
        #pragma unroll
        for (int ks = 0; ks < 2; ks++) {
            uint32_t fah[4][4], fal[4][4], fb[4][2];
            #pragma unroll
            for (int mi = 0; mi < 4; mi++) {
                const int row = wm * 64 + mi * 16 + (lane & 15);
                const uint32_t off = row * SROWB + ks * 32 + (lane >> 4) * 16;
                ldmatrix_x4(fah[mi], tAh + off);
                ldmatrix_x4(fal[mi], tAl + off);
            }
            #pragma unroll
            for (int ni = 0; ni < 4; ni++) {
                const int nrow = wn * 32 + ni * 8 + (lane & 7);
                const uint32_t off = nrow * SROWB + ks * 32 + ((lane >> 3) & 1) * 16;
                ldmatrix_x2(fb[ni], tBh + off);
            }
            #pragma unroll
            for (int mi = 0; mi < 4; mi++)
                #pragma unroll
                for (int ni = 0; ni < 4; ni++) {
                    mma_f16(acc[mi][ni], fah[mi], fb[ni][0], fb[ni][1]);
                    mma_f16(acc[mi][ni], fal[mi], fb[ni][0], fb[ni][1]);
                }
        }
    };

    // 3-stage pipeline, one sync per chunk
    load_chunk(0, 0);
    load_chunk(1, 1);
    for (int c = 0; c < NCH; c++) {
        const int s = c % 3;
        if (c + 1 < NCH) cp_wait<1>(); else cp_wait<0>();
        __syncthreads();
        compute(s);
        if (c + 2 < NCH) load_chunk(c + 2, (c + 2) % 3);
    }

    // ---- epilogue ----
    if (mode == 0) {
        #pragma unroll
        for (int mi = 0; mi < 4; mi++) {
            const int r0 = bm + wm * 64 + mi * 16 + (lane >> 2);
            #pragma unroll
            for (int ni = 0; ni < 4; ni++) {
                const int c0 = bn + wn * 32 + ni * 8 + (lane & 3) * 2;
                const float2 bv = *(const float2*)(bias + c0);
                float2 o0, o1;
                o0.x = acc[mi][ni][0] + bv.x;
                o0.y = acc[mi][ni][1] + bv.y;
                o1.x = acc[mi][ni][2] + bv.x;
                o1.y = acc[mi][ni][3] + bv.y;
                *(float2*)(C + (size_t)r0 * N + c0) = o0;
                *(float2*)(C + (size_t)(r0 + 8) * N + c0) = o1;
            }
        }
    } else {
        // QKV fused: cols [0,1024)=q, [1024,2048)=k, [2048,3072)=v
        const int region = bn >> 10;   // uniform per CTA
        #pragma unroll
        for (int mi = 0; mi < 4; mi++) {
            const int r0 = bm + wm * 64 + mi * 16 + (lane >> 2);
            #pragma unroll
            for (int ni = 0; ni < 4; ni++) {
                const int c0 = bn + wn * 32 + ni * 8 + (lane & 3) * 2;
                const float2 bv = *(const float2*)(bias + c0);
                const int hh = (c0 & 1023) >> 6, d = c0 & 63;
                #pragma unroll
                for (int rr = 0; rr < 2; rr++) {
                    const int r = r0 + rr * 8;
                    const int b = r >> 11, sl = r & (SL - 1);
                    const size_t off = ((size_t)(b * NH + hh) * SL + sl) * HD + d;
                    float v0 = acc[mi][ni][2 * rr + 0] + bv.x;
                    float v1 = acc[mi][ni][2 * rr + 1] + bv.y;
                    if (region == 0) {
                        v0 *= 0.125f; v1 *= 0.125f;
                        uint32_t hi, lo;
                        split2h(v0, v1, hi, lo);
                        *(uint32_t*)(qh + off) = hi;
                        *(uint32_t*)(ql + off) = lo;
                    } else if (region == 1) {
                        *(uint32_t*)(kh + off) = pack2h(v0, v1);
                    } else {
                        *(uint32_t*)(vf + off) = pack2h(v0, v1);
                    }
                }
            }
        }
    }
}

// ---------------- HMMA flash attention (fp16x2, causal, 3-stage) ----------------
#define ABQ 128
#define ABK 64
#define ASTR 144
#define ATILEB (64 * ASTR)        // 9216
#define ASTAGEB (2 * ATILEB)      // 18432: Kh, Vth
#define ATTN_SMEM (3 * ASTAGEB)   // 55296 (dynamic)

__global__ __launch_bounds__(256) void attn_mma_kernel(
    const __half* __restrict__ Qh, const __half* __restrict__ Ql,
    const __half* __restrict__ Kh, const __half* __restrict__ Vth,
    __half* __restrict__ yh, __half* __restrict__ yl)
{
    extern __shared__ __align__(128) char smem[];
    const int tid = threadIdx.x;
    const int wq = tid >> 5;
    const int lane = tid & 31;
    const int bh = blockIdx.y;
    const int b = bh >> 4, h = bh & 15;
    const int qt = gridDim.x - 1 - blockIdx.x;   // heavy tiles first
    const int q0 = qt * ABQ;
    const uint32_t sbase = smem_u32(smem);

    const __half* Qhb = Qh + (size_t)bh * SL * HD;
    const __half* Qlb = Ql + (size_t)bh * SL * HD;
    const __half* Khb = Kh + (size_t)bh * SL * HD;
    const __half* Vthb = Vth + (size_t)bh * HD * SL;

    // ---- load Q tile (128 rows x 128B, hi/lo), extract A fragments ----
    uint32_t qfh[4][4], qfl[4][4];
    {
        const uint32_t qlo = sbase + 128 * ASTR;   // +18432
        #pragma unroll
        for (int i = 0; i < 4; i++) {
            const int lin = tid + 256 * i;         // 0..1023
            const int row = lin >> 3, g = lin & 7;
            cp_async16(sbase + row * ASTR + g * 16,
                       Qhb + (size_t)(q0 + row) * HD + g * 8);
            cp_async16(qlo + row * ASTR + g * 16,
                       Qlb + (size_t)(q0 + row) * HD + g * 8);
        }
        cp_commit();
        cp_wait<0>();
        __syncthreads();
        #pragma unroll
        for (int ks = 0; ks < 4; ks++) {
            const uint32_t off = (wq * 16 + (lane & 15)) * ASTR + ks * 32 + (lane >> 4) * 16;
            ldmatrix_x4(qfh[ks], sbase + off);
            ldmatrix_x4(qfl[ks], qlo + off);
        }
        __syncthreads();
    }

    auto load_kv = [&](int t, int st) {
        const uint32_t sb = sbase + st * ASTAGEB;
        const int k0 = t * ABK;
        #pragma unroll
        for (int i = 0; i < 2; i++) {
            const int lin = tid + 256 * i;         // 0..511
            const int row = lin >> 3, g = lin & 7;
            const uint32_t ro = row * ASTR + g * 16;
            cp_async16(sb + 0 * ATILEB + ro, Khb  + (size_t)(k0 + row) * HD + g * 8);
            cp_async16(sb + 1 * ATILEB + ro, Vthb + (size_t)row * SL + k0 + g * 8);
        }
        cp_commit();
    };

    float o[8][4];
    #pragma unroll
    for (int j = 0; j < 8; j++)
        #pragma unroll
        for (int e = 0; e < 4; e++) o[j][e] = 0.f;
    float m0 = -1e30f, m1 = -1e30f, l0 = 0.f, l1 = 0.f;

    const int ntiles = 2 * qt + 2;
    load_kv(0, 0);
    load_kv(1, 1);

    for (int t = 0; t < ntiles; t++) {
        const int s = t % 3;
        if (t + 1 < ntiles) cp_wait<1>(); else cp_wait<0>();
        __syncthreads();
        const uint32_t sb = sbase + s * ASTAGEB;

        // ---- S = Qh.K + Ql.K ----
        float sacc[8][4];
        #pragma unroll
        for (int j = 0; j < 8; j++)
            #pragma unroll
            for (int e = 0; e < 4; e++) sacc[j][e] = 0.f;
        #pragma unroll
        for (int ks = 0; ks < 4; ks++) {
            #pragma unroll
            for (int nj = 0; nj < 4; nj++) {
                uint32_t fh[4];
                const uint32_t off = (nj * 16 + (lane & 15)) * ASTR + ks * 32 + (lane >> 4) * 16;
                ldmatrix_x4(fh, sb + off);
                mma_f16(sacc[2 * nj],     qfh[ks], fh[0], fh[2]);
                mma_f16(sacc[2 * nj],     qfl[ks], fh[0], fh[2]);
                mma_f16(sacc[2 * nj + 1], qfh[ks], fh[1], fh[3]);
                mma_f16(sacc[2 * nj + 1], qfl[ks], fh[1], fh[3]);
            }
        }

        // ---- causal mask ----
        const int k0 = t * ABK;
        const int row0 = q0 + wq * 16 + (lane >> 2);
        if (k0 + ABK - 1 > q0 + wq * 16) {
            #pragma unroll
            for (int ni = 0; ni < 8; ni++) {
                const int c0 = k0 + ni * 8 + (lane & 3) * 2;
                if (c0 > row0)         sacc[ni][0] = -1e30f;
                if (c0 + 1 > row0)     sacc[ni][1] = -1e30f;
                if (c0 > row0 + 8)     sacc[ni][2] = -1e30f;
                if (c0 + 1 > row0 + 8) sacc[ni][3] = -1e30f;
            }
        }

        // ---- online softmax ----
        float mt0 = -1e30f, mt1 = -1e30f;
        #pragma unroll
        for (int ni = 0; ni < 8; ni++) {
            mt0 = fmaxf(mt0, fmaxf(sacc[ni][0], sacc[ni][1]));
            mt1 = fmaxf(mt1, fmaxf(sacc[ni][2], sacc[ni][3]));
        }
        mt0 = fmaxf(mt0, __shfl_xor_sync(0xFFFFFFFFu, mt0, 1));
        mt0 = fmaxf(mt0, __shfl_xor_sync(0xFFFFFFFFu, mt0, 2));
        mt1 = fmaxf(mt1, __shfl_xor_sync(0xFFFFFFFFu, mt1, 1));
        mt1 = fmaxf(mt1, __shfl_xor_sync(0xFFFFFFFFu, mt1, 2));
        const float mn0 = fmaxf(m0, mt0), mn1 = fmaxf(m1, mt1);
        const float cr0 = __expf(m0 - mn0), cr1 = __expf(m1 - mn1);
        float ps0 = 0.f, ps1 = 0.f;
        #pragma unroll
        for (int ni = 0; ni < 8; ni++) {
            sacc[ni][0] = __expf(sacc[ni][0] - mn0); ps0 += sacc[ni][0];
            sacc[ni][1] = __expf(sacc[ni][1] - mn0); ps0 += sacc[ni][1];
            sacc[ni][2] = __expf(sacc[ni][2] - mn1); ps1 += sacc[ni][2];
            sacc[ni][3] = __expf(sacc[ni][3] - mn1); ps1 += sacc[ni][3];
        }
        ps0 += __shfl_xor_sync(0xFFFFFFFFu, ps0, 1);
        ps0 += __shfl_xor_sync(0xFFFFFFFFu, ps0, 2);
        ps1 += __shfl_xor_sync(0xFFFFFFFFu, ps1, 1);
        ps1 += __shfl_xor_sync(0xFFFFFFFFu, ps1, 2);
        l0 = l0 * cr0 + ps0; l1 = l1 * cr1 + ps1;
        m0 = mn0; m1 = mn1;
        #pragma unroll
        for (int j = 0; j < 8; j++) {
            o[j][0] *= cr0; o[j][1] *= cr0;
            o[j][2] *= cr1; o[j][3] *= cr1;
        }

        // ---- pack P into A fragments (hi/lo fp16) ----
        uint32_t pph[4][4], ppl[4][4];
        #pragma unroll
        for (int kt = 0; kt < 4; kt++) {
            split2h(sacc[2 * kt][0],     sacc[2 * kt][1],     pph[kt][0], ppl[kt][0]);
            split2h(sacc[2 * kt][2],     sacc[2 * kt][3],     pph[kt][1], ppl[kt][1]);
            split2h(sacc[2 * kt + 1][0], sacc[2 * kt + 1][1], pph[kt][2], ppl[kt][2]);
            split2h(sacc[2 * kt + 1][2], sacc[2 * kt + 1][3], pph[kt][3], ppl[kt][3]);
        }

        // ---- O += Ph.V + Pl.V ----
        #pragma unroll
        for (int kt = 0; kt < 4; kt++) {
            #pragma unroll
            for (int nj = 0; nj < 4; nj++) {
                uint32_t fh[4];
                const uint32_t off = (nj * 16 + (lane & 15)) * ASTR + kt * 32 + (lane >> 4) * 16;
                ldmatrix_x4(fh, sb + ATILEB + off);
                mma_f16(o[2 * nj],     pph[kt], fh[0], fh[2]);
                mma_f16(o[2 * nj],     ppl[kt], fh[0], fh[2]);
                mma_f16(o[2 * nj + 1], pph[kt], fh[1], fh[3]);
                mma_f16(o[2 * nj + 1], ppl[kt], fh[1], fh[3]);
            }
        }

        if (t + 2 < ntiles) load_kv(t + 2, (t + 2) % 3);
    }

    // ---- epilogue: normalize + fp16-split write to yh/yl [b, s, ne] ----
    const float i0 = 1.f / l0, i1 = 1.f / l1;
    const int row = q0 + wq * 16 + (lane >> 2);
    const size_t b0 = ((size_t)(b * SL + row)) * NE + h * HD;
    const size_t b1 = b0 + (size_t)8 * NE;
    #pragma unroll
    for (int j = 0; j < 8; j++) {
        const int col = j * 8 + (lane & 3) * 2;
        uint32_t hi, lo;
        split2h(o[j][0] * i0, o[j][1] * i0, hi, lo);
        *(uint32_t*)(yh + b0 + col) = hi;
        *(uint32_t*)(yl + b0 + col) = lo;
        split2h(o[j][2] * i1, o[j][3] * i1, hi, lo);
        *(uint32_t*)(yh + b1 + col) = hi;
        *(uint32_t*)(yl + b1 + col) = lo;
    }
}

// ---------------- launch ----------------
extern "C" void kernel_launch(void* const* d_in, const int* in_sizes, int n_in,
                              void* d_out, int out_size)
{
    const float* x    = (const float*)d_in[0];
    const float* Wqkv = (const float*)d_in[2];
    const float* bqkv = (const float*)d_in[3];
    const float* Wo   = (const float*)d_in[4];
    const float* bo   = (const float*)d_in[5];
    float* out = (float*)d_out;

    __half *xh, *xl, *yh, *yl, *wqh, *woh;
    __half *aqh, *aql, *akh, *avf, *avth;
    cudaGetSymbolAddress((void**)&xh, g_xh);
    cudaGetSymbolAddress((void**)&xl, g_xl);
    cudaGetSymbolAddress((void**)&yh, g_yh);
    cudaGetSymbolAddress((void**)&yl, g_yl);
    cudaGetSymbolAddress((void**)&wqh, g_wqh);
    cudaGetSymbolAddress((void**)&woh, g_woh);
    cudaGetSymbolAddress((void**)&aqh, g_aqh);
    cudaGetSymbolAddress((void**)&aql, g_aql);
    cudaGetSymbolAddress((void**)&akh, g_akh);
    cudaGetSymbolAddress((void**)&avf, g_avf);
    cudaGetSymbolAddress((void**)&avth, g_avth);

    cudaFuncSetAttribute(gemm_f16x2, cudaFuncAttributeMaxDynamicSharedMemorySize, GEMM_SMEM);
    cudaFuncSetAttribute(attn_mma_kernel, cudaFuncAttributeMaxDynamicSharedMemorySize, ATTN_SMEM);

    // splits
    split_kernel<<<(MROWS * NE / 4 + 255) / 256, 256>>>(x, xh, xl, MROWS * NE / 4);
    tsplit_kernel<<<dim3(3 * NE / 32, NE / 32), 256>>>(Wqkv, wqh, NE, 3 * NE);
    tsplit_kernel<<<dim3(NE / 32, NE / 32), 256>>>(Wo, woh, NE, NE);

    // 1) QKV projection, fused epilogue -> aqh/aql/akh/avf
    gemm_f16x2<<<dim3(3 * NE / 128, MROWS / 128), 256, GEMM_SMEM>>>(
        xh, xl, wqh, bqkv, nullptr, 3 * NE, 1, aqh, aql, akh, avf);

    // 2) V transpose (fp16)
    vt_prep<<<dim3(SL / 32, HD / 32, BHN), 256>>>(avf, avth);

    // 3) causal flash attention -> yh/yl (fp16 split)
    attn_mma_kernel<<<dim3(SL / ABQ, BHN), 256, ATTN_SMEM>>>(
        aqh, aql, akh, avth, yh, yl);

    // 4) output projection
    gemm_f16x2<<<dim3(NE / 128, MROWS / 128), 256, GEMM_SMEM>>>(
        yh, yl, woh, bo, out, NE, 0, nullptr, nullptr, nullptr, nullptr);
}

// round 11
// speedup vs baseline: 6.0858x; 1.1001x over previous
#include <cuda_runtime.h>
#include <cuda_fp16.h>
#include <cstdint>

// Problem constants
#define BS 4
#define SL 2048
#define NE 1024
#define NH 16
#define HD 64
#define MROWS (BS*SL)          // 8192
#define GK 1024                // K dim for both GEMMs
#define BKC 32                 // K per chunk (fp16 elems)
#define NCH (GK / BKC)         // 32 chunks
#define BHN (BS * NH)          // 64

// ---------------- scratch (no allocs allowed) ----------------
__device__ __half g_xh[(size_t)MROWS * NE];
__device__ __half g_yh[(size_t)MROWS * NE];
__device__ __half g_wqh[(size_t)3 * NE * NE];     // [3072,1024] (transposed)
__device__ __half g_woh[(size_t)NE * NE];         // [1024,1024] (transposed)
// attention operands, per (b,h)
__device__ __half g_aqh[(size_t)BHN * SL * HD];   // Q (scaled) [bh][s][d]
__device__ __half g_akh[(size_t)BHN * SL * HD];   // K [bh][s][d]
__device__ __half g_avf[(size_t)BHN * SL * HD];   // V [bh][s][d]
__device__ __half g_avth[(size_t)BHN * HD * SL];  // V^T [bh][d][s]

// ---------------- helpers ----------------
__device__ __forceinline__ uint32_t smem_u32(const void* p) {
    uint32_t a;
    asm("{ .reg .u64 t; cvta.to.shared.u64 t, %1; cvt.u32.u64 %0, t; }" : "=r"(a) : "l"(p));
    return a;
}
__device__ __forceinline__ void cp_async16(uint32_t dst, const void* src) {
    asm volatile("cp.async.cg.shared.global [%0], [%1], 16;" :: "r"(dst), "l"(src) : "memory");
}
__device__ __forceinline__ void cp_commit() {
    asm volatile("cp.async.commit_group;" ::: "memory");
}
template<int N> __device__ __forceinline__ void cp_wait() {
    asm volatile("cp.async.wait_group %0;" :: "n"(N) : "memory");
}
__device__ __forceinline__ void ldmatrix_x4(uint32_t* r, uint32_t addr) {
    asm volatile("ldmatrix.sync.aligned.m8n8.x4.shared.b16 {%0,%1,%2,%3}, [%4];"
                 : "=r"(r[0]), "=r"(r[1]), "=r"(r[2]), "=r"(r[3]) : "r"(addr));
}
__device__ __forceinline__ void mma_f16(float* c, const uint32_t* a, uint32_t b0, uint32_t b1) {
    asm volatile(
        "mma.sync.aligned.m16n8k16.row.col.f32.f16.f16.f32 "
        "{%0,%1,%2,%3}, {%4,%5,%6,%7}, {%8,%9}, {%0,%1,%2,%3};"
        : "+f"(c[0]), "+f"(c[1]), "+f"(c[2]), "+f"(c[3])
        : "r"(a[0]), "r"(a[1]), "r"(a[2]), "r"(a[3]), "r"(b0), "r"(b1));
}
__device__ __forceinline__ uint32_t pack2h(float a, float b) {
    __half2 h2 = __floats2half2_rn(a, b);
    return *reinterpret_cast<uint32_t*>(&h2);
}

// ---------------- prep kernels ----------------
__global__ __launch_bounds__(256) void tofp16_kernel(
    const float* __restrict__ in, __half* __restrict__ out, int n4)
{
    int i = blockIdx.x * 256 + threadIdx.x;
    if (i >= n4) return;
    float4 v = ((const float4*)in)[i];
    uint32_t* O = (uint32_t*)out;
    O[2 * i + 0] = pack2h(v.x, v.y);
    O[2 * i + 1] = pack2h(v.z, v.w);
}

// transpose: W [Kd, Nd] fp32 -> Wt [Nd, Kd] fp16
__global__ __launch_bounds__(256) void tsplit_kernel(
    const float* __restrict__ W, __half* __restrict__ hi, int Kd, int Nd)
{
    __shared__ float t[32][33];
    const int tx = threadIdx.x & 31, ty = threadIdx.x >> 5;  // 32 x 8
    const int k0 = blockIdx.y * 32, n0 = blockIdx.x * 32;
    #pragma unroll
    for (int r = 0; r < 4; r++)
        t[ty + 8 * r][tx] = W[(size_t)(k0 + ty + 8 * r) * Nd + n0 + tx];
    __syncthreads();
    #pragma unroll
    for (int r = 0; r < 4; r++)
        hi[(size_t)(n0 + ty + 8 * r) * Kd + k0 + tx] = __float2half(t[tx][ty + 8 * r]);
}

// V transpose (fp16): Vf [bh][s][d] -> Vt [bh][d][s]
__global__ __launch_bounds__(256) void vt_prep(
    const __half* __restrict__ vf, __half* __restrict__ vth)
{
    __shared__ float t[32][33];
    const int tx = threadIdx.x & 31, ty = threadIdx.x >> 5;
    const int s0 = blockIdx.x * 32, d0 = blockIdx.y * 32, bh = blockIdx.z;
    #pragma unroll
    for (int r = 0; r < 4; r++)
        t[ty + 8 * r][tx] = __half2float(
            vf[((size_t)bh * SL + s0 + ty + 8 * r) * HD + d0 + tx]);
    __syncthreads();
    #pragma unroll
    for (int r = 0; r < 4; r++)
        vth[((size_t)bh * HD + d0 + ty + 8 * r) * SL + s0 + tx] =
            __float2half(t[tx][ty + 8 * r]);
}

// ---------------- HMMA fp16 GEMM, 4-stage pipeline, warp tile 32x64 ----------
// mode 0: C = A@B + bias (float out). mode 1: QKV fused epilogue.
#define SROWB 80                       // 64B data + 16B pad
#define TILEB (128 * SROWB)            // 10240
#define STAGEB (2 * TILEB)             // A, B = 20480
#define NSTG 4
#define GEMM_SMEM (NSTG * STAGEB)      // 81920

__global__ __launch_bounds__(256)
void gemm_f16(const __half* __restrict__ A, const __half* __restrict__ B,
              const float* __restrict__ bias, float* __restrict__ C, int N,
              int mode, __half* __restrict__ qh, __half* __restrict__ kh,
              __half* __restrict__ vf)
{
    extern __shared__ __align__(128) char smem[];
    const int tid = threadIdx.x;
    const int wid = tid >> 5;
    const int lane = tid & 31;
    const int bm = blockIdx.y * 128;
    const int bn = blockIdx.x * 128;
    const uint32_t sbase = smem_u32(smem);

    const int wm = wid & 3;    // 4 m-warps of 32 rows
    const int wn = wid >> 2;   // 2 n-warps of 64 cols

    float acc[2][8][4];
    #pragma unroll
    for (int mi = 0; mi < 2; mi++)
        #pragma unroll
        for (int ni = 0; ni < 8; ni++)
            #pragma unroll
            for (int e = 0; e < 4; e++) acc[mi][ni][e] = 0.f;

    auto load_chunk = [&](int c, int st) {
        const uint32_t sb = sbase + st * STAGEB;
        #pragma unroll
        for (int i = 0; i < 2; i++) {
            const int lin = tid + 256 * i;            // 0..511
            const int row = lin >> 2, g = lin & 3;
            cp_async16(sb + row * SROWB + g * 16,
                       A + (size_t)(bm + row) * GK + c * BKC + g * 8);
            cp_async16(sb + TILEB + row * SROWB + g * 16,
                       B + (size_t)(bn + row) * GK + c * BKC + g * 8);
        }
        cp_commit();
    };

    auto compute = [&](int st) {
        const uint32_t tA = sbase + st * STAGEB;
        const uint32_t tB = tA + TILEB;
        #pragma unroll
        for (int ks = 0; ks < 2; ks++) {
            uint32_t fa[2][4], fb[4][4];
            #pragma unroll
            for (int mi = 0; mi < 2; mi++) {
                const int row = wm * 32 + mi * 16 + (lane & 15);
                const uint32_t off = row * SROWB + ks * 32 + (lane >> 4) * 16;
                ldmatrix_x4(fa[mi], tA + off);
            }
            #pragma unroll
            for (int njp = 0; njp < 4; njp++) {
                const int mat = lane >> 3;   // 0..3
                const int nrow = wn * 64 + njp * 16 + (mat >> 1) * 8 + (lane & 7);
                const uint32_t off = nrow * SROWB + ks * 32 + (mat & 1) * 16;
                ldmatrix_x4(fb[njp], tB + off);
            }
            #pragma unroll
            for (int mi = 0; mi < 2; mi++)
                #pragma unroll
                for (int njp = 0; njp < 4; njp++) {
                    mma_f16(acc[mi][2 * njp],     fa[mi], fb[njp][0], fb[njp][1]);
                    mma_f16(acc[mi][2 * njp + 1], fa[mi], fb[njp][2], fb[njp][3]);
                }
        }
    };

    // 4-stage pipeline, one sync per chunk
    load_chunk(0, 0);
    load_chunk(1, 1);
    load_chunk(2, 2);
    for (int c = 0; c < NCH; c++) {
        const int s = c % NSTG;
        if (c + 2 < NCH) cp_wait<2>();
        else if (c + 1 < NCH) cp_wait<1>();
        else cp_wait<0>();
        __syncthreads();
        compute(s);
        if (c + 3 < NCH) load_chunk(c + 3, (c + 3) % NSTG);
    }

    // ---- epilogue ----
    if (mode == 0) {
        #pragma unroll
        for (int mi = 0; mi < 2; mi++) {
            const int r0 = bm + wm * 32 + mi * 16 + (lane >> 2);
            #pragma unroll
            for (int ni = 0; ni < 8; ni++) {
                const int c0 = bn + wn * 64 + ni * 8 + (lane & 3) * 2;
                const float2 bv = *(const float2*)(bias + c0);
                float2 o0, o1;
                o0.x = acc[mi][ni][0] + bv.x;
                o0.y = acc[mi][ni][1] + bv.y;
                o1.x = acc[mi][ni][2] + bv.x;
                o1.y = acc[mi][ni][3] + bv.y;
                *(float2*)(C + (size_t)r0 * N + c0) = o0;
                *(float2*)(C + (size_t)(r0 + 8) * N + c0) = o1;
            }
        }
    } else {
        // QKV fused: cols [0,1024)=q (scaled), [1024,2048)=k, [2048,3072)=v
        const int region = bn >> 10;   // uniform per CTA
        #pragma unroll
        for (int mi = 0; mi < 2; mi++) {
            const int r0 = bm + wm * 32 + mi * 16 + (lane >> 2);
            #pragma unroll
            for (int ni = 0; ni < 8; ni++) {
                const int c0 = bn + wn * 64 + ni * 8 + (lane & 3) * 2;
                const float2 bv = *(const float2*)(bias + c0);
                const int hh = (c0 & 1023) >> 6, d = c0 & 63;
                #pragma unroll
                for (int rr = 0; rr < 2; rr++) {
                    const int r = r0 + rr * 8;
                    const int b = r >> 11, sl = r & (SL - 1);
                    const size_t off = ((size_t)(b * NH + hh) * SL + sl) * HD + d;
                    float v0 = acc[mi][ni][2 * rr + 0] + bv.x;
                    float v1 = acc[mi][ni][2 * rr + 1] + bv.y;
                    if (region == 0) {
                        *(uint32_t*)(qh + off) = pack2h(v0 * 0.125f, v1 * 0.125f);
                    } else if (region == 1) {
                        *(uint32_t*)(kh + off) = pack2h(v0, v1);
                    } else {
                        *(uint32_t*)(vf + off) = pack2h(v0, v1);
                    }
                }
            }
        }
    }
}

// ---------------- HMMA flash attention (fp16, causal, 3-stage) ----------------
#define ABQ 128
#define ABK 64
#define ASTR 144
#define ATILEB (64 * ASTR)        // 9216
#define ASTAGEB (2 * ATILEB)      // 18432: K, Vt
#define ATTN_SMEM (3 * ASTAGEB)   // 55296

__global__ __launch_bounds__(256) void attn_mma_kernel(
    const __half* __restrict__ Qh, const __half* __restrict__ Kh,
    const __half* __restrict__ Vth, __half* __restrict__ yh)
{
    extern __shared__ __align__(128) char smem[];
    const int tid = threadIdx.x;
    const int wq = tid >> 5;
    const int lane = tid & 31;
    const int bh = blockIdx.y;
    const int b = bh >> 4, h = bh & 15;
    const int qt = gridDim.x - 1 - blockIdx.x;   // heavy tiles first
    const int q0 = qt * ABQ;
    const uint32_t sbase = smem_u32(smem);

    const __half* Qhb = Qh + (size_t)bh * SL * HD;
    const __half* Khb = Kh + (size_t)bh * SL * HD;
    const __half* Vthb = Vth + (size_t)bh * HD * SL;

    // ---- load Q tile (128 rows x 128B) into stage0, extract A fragments ----
    uint32_t qf[4][4];
    {
        #pragma unroll
        for (int i = 0; i < 4; i++) {
            const int lin = tid + 256 * i;         // 0..1023
            const int row = lin >> 3, g = lin & 7;
            cp_async16(sbase + row * ASTR + g * 16,
                       Qhb + (size_t)(q0 + row) * HD + g * 8);
        }
        cp_commit();
        cp_wait<0>();
        __syncthreads();
        #pragma unroll
        for (int ks = 0; ks < 4; ks++) {
            const uint32_t off = (wq * 16 + (lane & 15)) * ASTR + ks * 32 + (lane >> 4) * 16;
            ldmatrix_x4(qf[ks], sbase + off);
        }
        __syncthreads();
    }

    auto load_kv = [&](int t, int st) {
        const uint32_t sb = sbase + st * ASTAGEB;
        const int k0 = t * ABK;
        #pragma unroll
        for (int i = 0; i < 2; i++) {
            const int lin = tid + 256 * i;         // 0..511
            const int row = lin >> 3, g = lin & 7;
            const uint32_t ro = row * ASTR + g * 16;
            cp_async16(sb + 0 * ATILEB + ro, Khb  + (size_t)(k0 + row) * HD + g * 8);
            cp_async16(sb + 1 * ATILEB + ro, Vthb + (size_t)row * SL + k0 + g * 8);
        }
        cp_commit();
    };

    float o[8][4];
    #pragma unroll
    for (int j = 0; j < 8; j++)
        #pragma unroll
        for (int e = 0; e < 4; e++) o[j][e] = 0.f;
    float m0 = -1e30f, m1 = -1e30f, l0 = 0.f, l1 = 0.f;

    const int ntiles = 2 * qt + 2;
    load_kv(0, 0);
    load_kv(1, 1);

    for (int t = 0; t < ntiles; t++) {
        const int s = t % 3;
        if (t + 1 < ntiles) cp_wait<1>(); else cp_wait<0>();
        __syncthreads();
        const uint32_t sb = sbase + s * ASTAGEB;

        // ---- S = Q.K ----
        float sacc[8][4];
        #pragma unroll
        for (int j = 0; j < 8; j++)
            #pragma unroll
            for (int e = 0; e < 4; e++) sacc[j][e] = 0.f;
        #pragma unroll
        for (int ks = 0; ks < 4; ks++) {
            #pragma unroll
            for (int nj = 0; nj < 4; nj++) {
                uint32_t fh[4];
                const uint32_t off = (nj * 16 + (lane & 15)) * ASTR + ks * 32 + (lane >> 4) * 16;
                ldmatrix_x4(fh, sb + off);
                mma_f16(sacc[2 * nj],     qf[ks], fh[0], fh[2]);
                mma_f16(sacc[2 * nj + 1], qf[ks], fh[1], fh[3]);
            }
        }

        // ---- causal mask ----
        const int k0 = t * ABK;
        const int row0 = q0 + wq * 16 + (lane >> 2);
        if (k0 + ABK - 1 > q0 + wq * 16) {
            #pragma unroll
            for (int ni = 0; ni < 8; ni++) {
                const int c0 = k0 + ni * 8 + (lane & 3) * 2;
                if (c0 > row0)         sacc[ni][0] = -1e30f;
                if (c0 + 1 > row0)     sacc[ni][1] = -1e30f;
                if (c0 > row0 + 8)     sacc[ni][2] = -1e30f;
                if (c0 + 1 > row0 + 8) sacc[ni][3] = -1e30f;
            }
        }

        // ---- online softmax ----
        float mt0 = -1e30f, mt1 = -1e30f;
        #pragma unroll
        for (int ni = 0; ni < 8; ni++) {
            mt0 = fmaxf(mt0, fmaxf(sacc[ni][0], sacc[ni][1]));
            mt1 = fmaxf(mt1, fmaxf(sacc[ni][2], sacc[ni][3]));
        }
        mt0 = fmaxf(mt0, __shfl_xor_sync(0xFFFFFFFFu, mt0, 1));
        mt0 = fmaxf(mt0, __shfl_xor_sync(0xFFFFFFFFu, mt0, 2));
        mt1 = fmaxf(mt1, __shfl_xor_sync(0xFFFFFFFFu, mt1, 1));
        mt1 = fmaxf(mt1, __shfl_xor_sync(0xFFFFFFFFu, mt1, 2));
        const float mn0 = fmaxf(m0, mt0), mn1 = fmaxf(m1, mt1);
        const float cr0 = __expf(m0 - mn0), cr1 = __expf(m1 - mn1);
        float ps0 = 0.f, ps1 = 0.f;
        #pragma unroll
        for (int ni = 0; ni < 8; ni++) {
            sacc[ni][0] = __expf(sacc[ni][0] - mn0); ps0 += sacc[ni][0];
            sacc[ni][1] = __expf(sacc[ni][1] - mn0); ps0 += sacc[ni][1];
            sacc[ni][2] = __expf(sacc[ni][2] - mn1); ps1 += sacc[ni][2];
            sacc[ni][3] = __expf(sacc[ni][3] - mn1); ps1 += sacc[ni][3];
        }
        ps0 += __shfl_xor_sync(0xFFFFFFFFu, ps0, 1);
        ps0 += __shfl_xor_sync(0xFFFFFFFFu, ps0, 2);
        ps1 += __shfl_xor_sync(0xFFFFFFFFu, ps1, 1);
        ps1 += __shfl_xor_sync(0xFFFFFFFFu, ps1, 2);
        l0 = l0 * cr0 + ps0; l1 = l1 * cr1 + ps1;
        m0 = mn0; m1 = mn1;
        #pragma unroll
        for (int j = 0; j < 8; j++) {
            o[j][0] *= cr0; o[j][1] *= cr0;
            o[j][2] *= cr1; o[j][3] *= cr1;
        }

        // ---- pack P into A fragments (fp16) ----
        uint32_t pp[4][4];
        #pragma unroll
        for (int kt = 0; kt < 4; kt++) {
            pp[kt][0] = pack2h(sacc[2 * kt][0],     sacc[2 * kt][1]);
            pp[kt][1] = pack2h(sacc[2 * kt][2],     sacc[2 * kt][3]);
            pp[kt][2] = pack2h(sacc[2 * kt + 1][0], sacc[2 * kt + 1][1]);
            pp[kt][3] = pack2h(sacc[2 * kt + 1][2], sacc[2 * kt + 1][3]);
        }

        // ---- O += P.V ----
        #pragma unroll
        for (int kt = 0; kt < 4; kt++) {
            #pragma unroll
            for (int nj = 0; nj < 4; nj++) {
                uint32_t fh[4];
                const uint32_t off = (nj * 16 + (lane & 15)) * ASTR + kt * 32 + (lane >> 4) * 16;
                ldmatrix_x4(fh, sb + ATILEB + off);
                mma_f16(o[2 * nj],     pp[kt], fh[0], fh[2]);
                mma_f16(o[2 * nj + 1], pp[kt], fh[1], fh[3]);
            }
        }

        if (t + 2 < ntiles) load_kv(t + 2, (t + 2) % 3);
    }

    // ---- epilogue: normalize + fp16 write to yh [b, s, ne] ----
    const float i0 = 1.f / l0, i1 = 1.f / l1;
    const int row = q0 + wq * 16 + (lane >> 2);
    const size_t b0 = ((size_t)(b * SL + row)) * NE + h * HD;
    const size_t b1 = b0 + (size_t)8 * NE;
    #pragma unroll
    for (int j = 0; j < 8; j++) {
        const int col = j * 8 + (lane & 3) * 2;
        *(uint32_t*)(yh + b0 + col) = pack2h(o[j][0] * i0, o[j][1] * i0);
        *(uint32_t*)(yh + b1 + col) = pack2h(o[j][2] * i1, o[j][3] * i1);
    }
}

// ---------------- launch ----------------
extern "C" void kernel_launch(void* const* d_in, const int* in_sizes, int n_in,
                              void* d_out, int out_size)
{
    const float* x    = (const float*)d_in[0];
    const float* Wqkv = (const float*)d_in[2];
    const float* bqkv = (const float*)d_in[3];
    const float* Wo   = (const float*)d_in[4];
    const float* bo   = (const float*)d_in[5];
    float* out = (float*)d_out;

    __half *xh, *yh, *wqh, *woh, *aqh, *akh, *avf, *avth;
    cudaGetSymbolAddress((void**)&xh, g_xh);
    cudaGetSymbolAddress((void**)&yh, g_yh);
    cudaGetSymbolAddress((void**)&wqh, g_wqh);
    cudaGetSymbolAddress((void**)&woh, g_woh);
    cudaGetSymbolAddress((void**)&aqh, g_aqh);
    cudaGetSymbolAddress((void**)&akh, g_akh);
    cudaGetSymbolAddress((void**)&avf, g_avf);
    cudaGetSymbolAddress((void**)&avth, g_avth);

    cudaFuncSetAttribute(gemm_f16, cudaFuncAttributeMaxDynamicSharedMemorySize, GEMM_SMEM);
    cudaFuncSetAttribute(attn_mma_kernel, cudaFuncAttributeMaxDynamicSharedMemorySize, ATTN_SMEM);

    // preps
    tofp16_kernel<<<(MROWS * NE / 4 + 255) / 256, 256>>>(x, xh, MROWS * NE / 4);
    tsplit_kernel<<<dim3(3 * NE / 32, NE / 32), 256>>>(Wqkv, wqh, NE, 3 * NE);
    tsplit_kernel<<<dim3(NE / 32, NE / 32), 256>>>(Wo, woh, NE, NE);

    // 1) QKV projection, fused epilogue -> aqh/akh/avf
    gemm_f16<<<dim3(3 * NE / 128, MROWS / 128), 256, GEMM_SMEM>>>(
        xh, wqh, bqkv, nullptr, 3 * NE, 1, aqh, akh, avf);

    // 2) V transpose (fp16)
    vt_prep<<<dim3(SL / 32, HD / 32, BHN), 256>>>(avf, avth);

    // 3) causal flash attention -> yh (fp16)
    attn_mma_kernel<<<dim3(SL / ABQ, BHN), 256, ATTN_SMEM>>>(aqh, akh, avth, yh);

    // 4) output projection
    gemm_f16<<<dim3(NE / 128, MROWS / 128), 256, GEMM_SMEM>>>(
        yh, woh, bo, out, NE, 0, nullptr, nullptr, nullptr);
}

// round 12
// speedup vs baseline: 8.8694x; 1.4574x over previous
#include <cuda_runtime.h>
#include <cuda_fp16.h>
#include <cstdint>

// Problem constants
#define BS 4
#define SL 2048
#define NE 1024
#define NH 16
#define HD 64
#define MROWS (BS*SL)          // 8192
#define GK 1024                // K dim for both GEMMs
#define BKC 32                 // K per chunk (fp16 elems)
#define NCH (GK / BKC)         // 32 chunks
#define BHN (BS * NH)          // 64

// ---------------- scratch (no allocs allowed) ----------------
__device__ __half g_xh[(size_t)MROWS * NE];
__device__ __half g_yh[(size_t)MROWS * NE];
__device__ __half g_wqh[(size_t)3 * NE * NE];     // [3072,1024] (transposed)
__device__ __half g_woh[(size_t)NE * NE];         // [1024,1024] (transposed)
// attention operands, per (b,h)
__device__ __half g_aqh[(size_t)BHN * SL * HD];   // Q (scaled) [bh][s][d]
__device__ __half g_akh[(size_t)BHN * SL * HD];   // K [bh][s][d]
__device__ __half g_avf[(size_t)BHN * SL * HD];   // V [bh][s][d]
__device__ __half g_avth[(size_t)BHN * HD * SL];  // V^T [bh][d][s]

// ---------------- helpers ----------------
__device__ __forceinline__ uint32_t smem_u32(const void* p) {
    uint32_t a;
    asm("{ .reg .u64 t; cvta.to.shared.u64 t, %1; cvt.u32.u64 %0, t; }" : "=r"(a) : "l"(p));
    return a;
}
__device__ __forceinline__ void cp_async16(uint32_t dst, const void* src) {
    asm volatile("cp.async.cg.shared.global [%0], [%1], 16;" :: "r"(dst), "l"(src) : "memory");
}
__device__ __forceinline__ void cp_commit() {
    asm volatile("cp.async.commit_group;" ::: "memory");
}
template<int N> __device__ __forceinline__ void cp_wait() {
    asm volatile("cp.async.wait_group %0;" :: "n"(N) : "memory");
}
__device__ __forceinline__ void ldmatrix_x4(uint32_t* r, uint32_t addr) {
    asm volatile("ldmatrix.sync.aligned.m8n8.x4.shared.b16 {%0,%1,%2,%3}, [%4];"
                 : "=r"(r[0]), "=r"(r[1]), "=r"(r[2]), "=r"(r[3]) : "r"(addr));
}
__device__ __forceinline__ void ldmatrix_x2(uint32_t* r, uint32_t addr) {
    asm volatile("ldmatrix.sync.aligned.m8n8.x2.shared.b16 {%0,%1}, [%2];"
                 : "=r"(r[0]), "=r"(r[1]) : "r"(addr));
}
__device__ __forceinline__ void mma_f16(float* c, const uint32_t* a, uint32_t b0, uint32_t b1) {
    asm volatile(
        "mma.sync.aligned.m16n8k16.row.col.f32.f16.f16.f32 "
        "{%0,%1,%2,%3}, {%4,%5,%6,%7}, {%8,%9}, {%0,%1,%2,%3};"
        : "+f"(c[0]), "+f"(c[1]), "+f"(c[2]), "+f"(c[3])
        : "r"(a[0]), "r"(a[1]), "r"(a[2]), "r"(a[3]), "r"(b0), "r"(b1));
}
__device__ __forceinline__ uint32_t pack2h(float a, float b) {
    __half2 h2 = __floats2half2_rn(a, b);
    return *reinterpret_cast<uint32_t*>(&h2);
}

// ---------------- prep kernels ----------------
__global__ __launch_bounds__(256) void tofp16_kernel(
    const float* __restrict__ in, __half* __restrict__ out, int n4)
{
    int i = blockIdx.x * 256 + threadIdx.x;
    if (i >= n4) return;
    float4 v = ((const float4*)in)[i];
    uint32_t* O = (uint32_t*)out;
    O[2 * i + 0] = pack2h(v.x, v.y);
    O[2 * i + 1] = pack2h(v.z, v.w);
}

// transpose: W [Kd, Nd] fp32 -> Wt [Nd, Kd] fp16
__global__ __launch_bounds__(256) void tsplit_kernel(
    const float* __restrict__ W, __half* __restrict__ hi, int Kd, int Nd)
{
    __shared__ float t[32][33];
    const int tx = threadIdx.x & 31, ty = threadIdx.x >> 5;  // 32 x 8
    const int k0 = blockIdx.y * 32, n0 = blockIdx.x * 32;
    #pragma unroll
    for (int r = 0; r < 4; r++)
        t[ty + 8 * r][tx] = W[(size_t)(k0 + ty + 8 * r) * Nd + n0 + tx];
    __syncthreads();
    #pragma unroll
    for (int r = 0; r < 4; r++)
        hi[(size_t)(n0 + ty + 8 * r) * Kd + k0 + tx] = __float2half(t[tx][ty + 8 * r]);
}

// V transpose (fp16): Vf [bh][s][d] -> Vt [bh][d][s]
__global__ __launch_bounds__(256) void vt_prep(
    const __half* __restrict__ vf, __half* __restrict__ vth)
{
    __shared__ float t[32][33];
    const int tx = threadIdx.x & 31, ty = threadIdx.x >> 5;
    const int s0 = blockIdx.x * 32, d0 = blockIdx.y * 32, bh = blockIdx.z;
    #pragma unroll
    for (int r = 0; r < 4; r++)
        t[ty + 8 * r][tx] = __half2float(
            vf[((size_t)bh * SL + s0 + ty + 8 * r) * HD + d0 + tx]);
    __syncthreads();
    #pragma unroll
    for (int r = 0; r < 4; r++)
        vth[((size_t)bh * HD + d0 + ty + 8 * r) * SL + s0 + tx] =
            __float2half(t[tx][ty + 8 * r]);
}

// ---------------- HMMA fp16 GEMM, 4-stage pipeline, warp tile 64x32 ----------
// (R10-validated warp layout, single A term)
// mode 0: C = A@B + bias (float out). mode 1: QKV fused epilogue.
#define SROWB 80                       // 64B data + 16B pad
#define TILEB (128 * SROWB)            // 10240
#define STAGEB (2 * TILEB)             // A, B = 20480
#define NSTG 4
#define GEMM_SMEM (NSTG * STAGEB)      // 81920

__global__ __launch_bounds__(256)
void gemm_f16(const __half* __restrict__ A, const __half* __restrict__ B,
              const float* __restrict__ bias, float* __restrict__ C, int N,
              int mode, __half* __restrict__ qh, __half* __restrict__ kh,
              __half* __restrict__ vf)
{
    extern __shared__ __align__(128) char smem[];
    const int tid = threadIdx.x;
    const int wid = tid >> 5;
    const int lane = tid & 31;
    const int bm = blockIdx.y * 128;
    const int bn = blockIdx.x * 128;
    const uint32_t sbase = smem_u32(smem);

    const int wm = wid & 1;    // 2 m-warps of 64 rows
    const int wn = wid >> 1;   // 4 n-warps of 32 cols

    float acc[4][4][4];
    #pragma unroll
    for (int mi = 0; mi < 4; mi++)
        #pragma unroll
        for (int ni = 0; ni < 4; ni++)
            #pragma unroll
            for (int e = 0; e < 4; e++) acc[mi][ni][e] = 0.f;

    auto load_chunk = [&](int c, int st) {
        const uint32_t sb = sbase + st * STAGEB;
        #pragma unroll
        for (int i = 0; i < 2; i++) {
            const int lin = tid + 256 * i;            // 0..511
            const int row = lin >> 2, g = lin & 3;
            cp_async16(sb + row * SROWB + g * 16,
                       A + (size_t)(bm + row) * GK + c * BKC + g * 8);
            cp_async16(sb + TILEB + row * SROWB + g * 16,
                       B + (size_t)(bn + row) * GK + c * BKC + g * 8);
        }
        cp_commit();
    };

    auto compute = [&](int st) {
        const uint32_t tA = sbase + st * STAGEB;
        const uint32_t tB = tA + TILEB;
        #pragma unroll
        for (int ks = 0; ks < 2; ks++) {
            uint32_t fa[4][4], fb[4][2];
            #pragma unroll
            for (int mi = 0; mi < 4; mi++) {
                const int row = wm * 64 + mi * 16 + (lane & 15);
                const uint32_t off = row * SROWB + ks * 32 + (lane >> 4) * 16;
                ldmatrix_x4(fa[mi], tA + off);
            }
            #pragma unroll
            for (int ni = 0; ni < 4; ni++) {
                const int nrow = wn * 32 + ni * 8 + (lane & 7);
                const uint32_t off = nrow * SROWB + ks * 32 + ((lane >> 3) & 1) * 16;
                ldmatrix_x2(fb[ni], tB + off);
            }
            #pragma unroll
            for (int mi = 0; mi < 4; mi++)
                #pragma unroll
                for (int ni = 0; ni < 4; ni++)
                    mma_f16(acc[mi][ni], fa[mi], fb[ni][0], fb[ni][1]);
        }
    };

    // 4-stage pipeline, one sync per chunk
    load_chunk(0, 0);
    load_chunk(1, 1);
    load_chunk(2, 2);
    for (int c = 0; c < NCH; c++) {
        const int s = c % NSTG;
        if (c + 2 < NCH) cp_wait<2>();
        else if (c + 1 < NCH) cp_wait<1>();
        else cp_wait<0>();
        __syncthreads();
        compute(s);
        if (c + 3 < NCH) load_chunk(c + 3, (c + 3) % NSTG);
    }

    // ---- epilogue ----
    if (mode == 0) {
        #pragma unroll
        for (int mi = 0; mi < 4; mi++) {
            const int r0 = bm + wm * 64 + mi * 16 + (lane >> 2);
            #pragma unroll
            for (int ni = 0; ni < 4; ni++) {
                const int c0 = bn + wn * 32 + ni * 8 + (lane & 3) * 2;
                const float2 bv = *(const float2*)(bias + c0);
                float2 o0, o1;
                o0.x = acc[mi][ni][0] + bv.x;
                o0.y = acc[mi][ni][1] + bv.y;
                o1.x = acc[mi][ni][2] + bv.x;
                o1.y = acc[mi][ni][3] + bv.y;
                *(float2*)(C + (size_t)r0 * N + c0) = o0;
                *(float2*)(C + (size_t)(r0 + 8) * N + c0) = o1;
            }
        }
    } else {
        // QKV fused: cols [0,1024)=q (scaled), [1024,2048)=k, [2048,3072)=v
        const int region = bn >> 10;   // uniform per CTA
        #pragma unroll
        for (int mi = 0; mi < 4; mi++) {
            const int r0 = bm + wm * 64 + mi * 16 + (lane >> 2);
            #pragma unroll
            for (int ni = 0; ni < 4; ni++) {
                const int c0 = bn + wn * 32 + ni * 8 + (lane & 3) * 2;
                const float2 bv = *(const float2*)(bias + c0);
                const int hh = (c0 & 1023) >> 6, d = c0 & 63;
                #pragma unroll
                for (int rr = 0; rr < 2; rr++) {
                    const int r = r0 + rr * 8;
                    const int b = r >> 11, sl = r & (SL - 1);
                    const size_t off = ((size_t)(b * NH + hh) * SL + sl) * HD + d;
                    float v0 = acc[mi][ni][2 * rr + 0] + bv.x;
                    float v1 = acc[mi][ni][2 * rr + 1] + bv.y;
                    if (region == 0) {
                        *(uint32_t*)(qh + off) = pack2h(v0 * 0.125f, v1 * 0.125f);
                    } else if (region == 1) {
                        *(uint32_t*)(kh + off) = pack2h(v0, v1);
                    } else {
                        *(uint32_t*)(vf + off) = pack2h(v0, v1);
                    }
                }
            }
        }
    }
}

// ---------------- HMMA flash attention (fp16, causal, 3-stage) ----------------
#define ABQ 128
#define ABK 64
#define ASTR 144
#define ATILEB (64 * ASTR)        // 9216
#define ASTAGEB (2 * ATILEB)      // 18432: K, Vt
#define ATTN_SMEM (3 * ASTAGEB)   // 55296

__global__ __launch_bounds__(256) void attn_mma_kernel(
    const __half* __restrict__ Qh, const __half* __restrict__ Kh,
    const __half* __restrict__ Vth, __half* __restrict__ yh)
{
    extern __shared__ __align__(128) char smem[];
    const int tid = threadIdx.x;
    const int wq = tid >> 5;
    const int lane = tid & 31;
    const int bh = blockIdx.y;
    const int b = bh >> 4, h = bh & 15;
    const int qt = gridDim.x - 1 - blockIdx.x;   // heavy tiles first
    const int q0 = qt * ABQ;
    const uint32_t sbase = smem_u32(smem);

    const __half* Qhb = Qh + (size_t)bh * SL * HD;
    const __half* Khb = Kh + (size_t)bh * SL * HD;
    const __half* Vthb = Vth + (size_t)bh * HD * SL;

    // ---- load Q tile (128 rows x 128B) into stage0, extract A fragments ----
    uint32_t qf[4][4];
    {
        #pragma unroll
        for (int i = 0; i < 4; i++) {
            const int lin = tid + 256 * i;         // 0..1023
            const int row = lin >> 3, g = lin & 7;
            cp_async16(sbase + row * ASTR + g * 16,
                       Qhb + (size_t)(q0 + row) * HD + g * 8);
        }
        cp_commit();
        cp_wait<0>();
        __syncthreads();
        #pragma unroll
        for (int ks = 0; ks < 4; ks++) {
            const uint32_t off = (wq * 16 + (lane & 15)) * ASTR + ks * 32 + (lane >> 4) * 16;
            ldmatrix_x4(qf[ks], sbase + off);
        }
        __syncthreads();
    }

    auto load_kv = [&](int t, int st) {
        const uint32_t sb = sbase + st * ASTAGEB;
        const int k0 = t * ABK;
        #pragma unroll
        for (int i = 0; i < 2; i++) {
            const int lin = tid + 256 * i;         // 0..511
            const int row = lin >> 3, g = lin & 7;
            const uint32_t ro = row * ASTR + g * 16;
            cp_async16(sb + 0 * ATILEB + ro, Khb  + (size_t)(k0 + row) * HD + g * 8);
            cp_async16(sb + 1 * ATILEB + ro, Vthb + (size_t)row * SL + k0 + g * 8);
        }
        cp_commit();
    };

    float o[8][4];
    #pragma unroll
    for (int j = 0; j < 8; j++)
        #pragma unroll
        for (int e = 0; e < 4; e++) o[j][e] = 0.f;
    float m0 = -1e30f, m1 = -1e30f, l0 = 0.f, l1 = 0.f;

    const int ntiles = 2 * qt + 2;
    load_kv(0, 0);
    load_kv(1, 1);

    for (int t = 0; t < ntiles; t++) {
        const int s = t % 3;
        if (t + 1 < ntiles) cp_wait<1>(); else cp_wait<0>();
        __syncthreads();
        const uint32_t sb = sbase + s * ASTAGEB;

        // ---- S = Q.K ----
        float sacc[8][4];
        #pragma unroll
        for (int j = 0; j < 8; j++)
            #pragma unroll
            for (int e = 0; e < 4; e++) sacc[j][e] = 0.f;
        #pragma unroll
        for (int ks = 0; ks < 4; ks++) {
            #pragma unroll
            for (int nj = 0; nj < 4; nj++) {
                uint32_t fh[4];
                const uint32_t off = (nj * 16 + (lane & 15)) * ASTR + ks * 32 + (lane >> 4) * 16;
                ldmatrix_x4(fh, sb + off);
                mma_f16(sacc[2 * nj],     qf[ks], fh[0], fh[2]);
                mma_f16(sacc[2 * nj + 1], qf[ks], fh[1], fh[3]);
            }
        }

        // ---- causal mask ----
        const int k0 = t * ABK;
        const int row0 = q0 + wq * 16 + (lane >> 2);
        if (k0 + ABK - 1 > q0 + wq * 16) {
            #pragma unroll
            for (int ni = 0; ni < 8; ni++) {
                const int c0 = k0 + ni * 8 + (lane & 3) * 2;
                if (c0 > row0)         sacc[ni][0] = -1e30f;
                if (c0 + 1 > row0)     sacc[ni][1] = -1e30f;
                if (c0 > row0 + 8)     sacc[ni][2] = -1e30f;
                if (c0 + 1 > row0 + 8) sacc[ni][3] = -1e30f;
            }
        }

        // ---- online softmax ----
        float mt0 = -1e30f, mt1 = -1e30f;
        #pragma unroll
        for (int ni = 0; ni < 8; ni++) {
            mt0 = fmaxf(mt0, fmaxf(sacc[ni][0], sacc[ni][1]));
            mt1 = fmaxf(mt1, fmaxf(sacc[ni][2], sacc[ni][3]));
        }
        mt0 = fmaxf(mt0, __shfl_xor_sync(0xFFFFFFFFu, mt0, 1));
        mt0 = fmaxf(mt0, __shfl_xor_sync(0xFFFFFFFFu, mt0, 2));
        mt1 = fmaxf(mt1, __shfl_xor_sync(0xFFFFFFFFu, mt1, 1));
        mt1 = fmaxf(mt1, __shfl_xor_sync(0xFFFFFFFFu, mt1, 2));
        const float mn0 = fmaxf(m0, mt0), mn1 = fmaxf(m1, mt1);
        const float cr0 = __expf(m0 - mn0), cr1 = __expf(m1 - mn1);
        float ps0 = 0.f, ps1 = 0.f;
        #pragma unroll
        for (int ni = 0; ni < 8; ni++) {
            sacc[ni][0] = __expf(sacc[ni][0] - mn0); ps0 += sacc[ni][0];
            sacc[ni][1] = __expf(sacc[ni][1] - mn0); ps0 += sacc[ni][1];
            sacc[ni][2] = __expf(sacc[ni][2] - mn1); ps1 += sacc[ni][2];
            sacc[ni][3] = __expf(sacc[ni][3] - mn1); ps1 += sacc[ni][3];
        }
        ps0 += __shfl_xor_sync(0xFFFFFFFFu, ps0, 1);
        ps0 += __shfl_xor_sync(0xFFFFFFFFu, ps0, 2);
        ps1 += __shfl_xor_sync(0xFFFFFFFFu, ps1, 1);
        ps1 += __shfl_xor_sync(0xFFFFFFFFu, ps1, 2);
        l0 = l0 * cr0 + ps0; l1 = l1 * cr1 + ps1;
        m0 = mn0; m1 = mn1;
        #pragma unroll
        for (int j = 0; j < 8; j++) {
            o[j][0] *= cr0; o[j][1] *= cr0;
            o[j][2] *= cr1; o[j][3] *= cr1;
        }

        // ---- pack P into A fragments (fp16) ----
        uint32_t pp[4][4];
        #pragma unroll
        for (int kt = 0; kt < 4; kt++) {
            pp[kt][0] = pack2h(sacc[2 * kt][0],     sacc[2 * kt][1]);
            pp[kt][1] = pack2h(sacc[2 * kt][2],     sacc[2 * kt][3]);
            pp[kt][2] = pack2h(sacc[2 * kt + 1][0], sacc[2 * kt + 1][1]);
            pp[kt][3] = pack2h(sacc[2 * kt + 1][2], sacc[2 * kt + 1][3]);
        }

        // ---- O += P.V ----
        #pragma unroll
        for (int kt = 0; kt < 4; kt++) {
            #pragma unroll
            for (int nj = 0; nj < 4; nj++) {
                uint32_t fh[4];
                const uint32_t off = (nj * 16 + (lane & 15)) * ASTR + kt * 32 + (lane >> 4) * 16;
                ldmatrix_x4(fh, sb + ATILEB + off);
                mma_f16(o[2 * nj],     pp[kt], fh[0], fh[2]);
                mma_f16(o[2 * nj + 1], pp[kt], fh[1], fh[3]);
            }
        }

        if (t + 2 < ntiles) load_kv(t + 2, (t + 2) % 3);
    }

    // ---- epilogue: normalize + fp16 write to yh [b, s, ne] ----
    const float i0 = 1.f / l0, i1 = 1.f / l1;
    const int row = q0 + wq * 16 + (lane >> 2);
    const size_t b0 = ((size_t)(b * SL + row)) * NE + h * HD;
    const size_t b1 = b0 + (size_t)8 * NE;
    #pragma unroll
    for (int j = 0; j < 8; j++) {
        const int col = j * 8 + (lane & 3) * 2;
        *(uint32_t*)(yh + b0 + col) = pack2h(o[j][0] * i0, o[j][1] * i0);
        *(uint32_t*)(yh + b1 + col) = pack2h(o[j][2] * i1, o[j][3] * i1);
    }
}

// ---------------- launch ----------------
extern "C" void kernel_launch(void* const* d_in, const int* in_sizes, int n_in,
                              void* d_out, int out_size)
{
    const float* x    = (const float*)d_in[0];
    const float* Wqkv = (const float*)d_in[2];
    const float* bqkv = (const float*)d_in[3];
    const float* Wo   = (const float*)d_in[4];
    const float* bo   = (const float*)d_in[5];
    float* out = (float*)d_out;

    __half *xh, *yh, *wqh, *woh, *aqh, *akh, *avf, *avth;
    cudaGetSymbolAddress((void**)&xh, g_xh);
    cudaGetSymbolAddress((void**)&yh, g_yh);
    cudaGetSymbolAddress((void**)&wqh, g_wqh);
    cudaGetSymbolAddress((void**)&woh, g_woh);
    cudaGetSymbolAddress((void**)&aqh, g_aqh);
    cudaGetSymbolAddress((void**)&akh, g_akh);
    cudaGetSymbolAddress((void**)&avf, g_avf);
    cudaGetSymbolAddress((void**)&avth, g_avth);

    cudaFuncSetAttribute(gemm_f16, cudaFuncAttributeMaxDynamicSharedMemorySize, GEMM_SMEM);
    cudaFuncSetAttribute(attn_mma_kernel, cudaFuncAttributeMaxDynamicSharedMemorySize, ATTN_SMEM);

    // preps
    tofp16_kernel<<<(MROWS * NE / 4 + 255) / 256, 256>>>(x, xh, MROWS * NE / 4);
    tsplit_kernel<<<dim3(3 * NE / 32, NE / 32), 256>>>(Wqkv, wqh, NE, 3 * NE);
    tsplit_kernel<<<dim3(NE / 32, NE / 32), 256>>>(Wo, woh, NE, NE);

    // 1) QKV projection, fused epilogue -> aqh/akh/avf
    gemm_f16<<<dim3(3 * NE / 128, MROWS / 128), 256, GEMM_SMEM>>>(
        xh, wqh, bqkv, nullptr, 3 * NE, 1, aqh, akh, avf);

    // 2) V transpose (fp16)
    vt_prep<<<dim3(SL / 32, HD / 32, BHN), 256>>>(avf, avth);

    // 3) causal flash attention -> yh (fp16)
    attn_mma_kernel<<<dim3(SL / ABQ, BHN), 256, ATTN_SMEM>>>(aqh, akh, avth, yh);

    // 4) output projection
    gemm_f16<<<dim3(NE / 128, MROWS / 128), 256, GEMM_SMEM>>>(
        yh, woh, bo, out, NE, 0, nullptr, nullptr, nullptr);
}